// round 1
// baseline (speedup 1.0000x reference)
#include <cuda_runtime.h>

#define NNODES 100000
#define D      128
#define S      16
#define NBATCH 8192
#define TILE   16
#define FS_STR (TILE + 1)   // padded stride for feats smem
#define NTHREADS 256

// Scratch for layer-1 output (51.2 MB). __device__ global: allocation-guard legal.
__device__ float g_h1[(size_t)NNODES * D];

// ---------------------------------------------------------------------------
// Layer 1: h1 = relu( concat(x, max_s x[neigh]) @ W1 + b1 )  for ALL nodes.
// One persistent block per SM; W1 staged in smem once per block.
// ---------------------------------------------------------------------------
extern "C" __global__ void __launch_bounds__(NTHREADS, 1)
sage_layer1(const float* __restrict__ x, const int* __restrict__ nidx,
            const float* __restrict__ W1, const float* __restrict__ b1)
{
    extern __shared__ float smem[];
    float* Ws  = smem;                          // [256][128] = 128 KB
    float* fs  = Ws + 256 * 128;                // [256][FS_STR]
    int*   nbs = (int*)(fs + 256 * FS_STR);     // [TILE][S] = 256 ints

    const int tid = threadIdx.x;

    // Stage W1 into smem (once per block)
    {
        const float4* src = (const float4*)W1;
        float4* dst = (float4*)Ws;
        #pragma unroll
        for (int i = tid; i < 256 * 128 / 4; i += NTHREADS) dst[i] = src[i];
    }

    // GEMM-stage thread mapping: node n (0..15), output group jg (8 outputs)
    const int n  = tid >> 4;          // tid / 16
    const int jg = tid & 15;          // tid % 16
    float bias[8];
    #pragma unroll
    for (int u = 0; u < 8; u++) bias[u] = b1[jg * 8 + u];

    __syncthreads();

    const int numTiles = NNODES / TILE;   // 6250, exact
    for (int tile = blockIdx.x; tile < numTiles; tile += gridDim.x) {
        const int node0 = tile * TILE;

        // neighbor indices for this tile: 16 nodes x 16 samples = 256 ints
        nbs[tid] = nidx[node0 * S + tid];
        __syncthreads();

        // ---- gather + max-aggregate into fs (concat layout, k-major) ----
        // 512 (node, d4) items, 2 per thread. nn constant within a warp ->
        // all 17 row loads are coalesced 512B LDG.128 bursts, 16-way MLP.
        #pragma unroll
        for (int it = 0; it < 2; it++) {
            const int lin = tid + it * NTHREADS;     // 0..511
            const int nn  = lin >> 5;                // node 0..15
            const int d4  = lin & 31;                // float4 group 0..31
            const float4* xs = (const float4*)(x + (size_t)(node0 + nn) * D) + d4;
            float4 self = *xs;
            const int* nb = &nbs[nn * S];
            float4 v0 = *((const float4*)(x + (size_t)nb[0] * D) + d4);
            float4 m = v0;
            #pragma unroll
            for (int s = 1; s < S; s++) {
                float4 v = *((const float4*)(x + (size_t)nb[s] * D) + d4);
                m.x = fmaxf(m.x, v.x); m.y = fmaxf(m.y, v.y);
                m.z = fmaxf(m.z, v.z); m.w = fmaxf(m.w, v.w);
            }
            const int d = d4 * 4;
            fs[(d + 0) * FS_STR + nn] = self.x;
            fs[(d + 1) * FS_STR + nn] = self.y;
            fs[(d + 2) * FS_STR + nn] = self.z;
            fs[(d + 3) * FS_STR + nn] = self.w;
            fs[(D + d + 0) * FS_STR + nn] = m.x;
            fs[(D + d + 1) * FS_STR + nn] = m.y;
            fs[(D + d + 2) * FS_STR + nn] = m.z;
            fs[(D + d + 3) * FS_STR + nn] = m.w;
        }
        __syncthreads();

        // ---- GEMV: 1 node x 8 outputs per thread ----
        float acc[8];
        #pragma unroll
        for (int u = 0; u < 8; u++) acc[u] = bias[u];

        #pragma unroll 8
        for (int k = 0; k < 256; k++) {
            const float f = fs[k * FS_STR + n];
            const float4 w0 = *((const float4*)(Ws + k * 128 + jg * 8));
            const float4 w1 = *((const float4*)(Ws + k * 128 + jg * 8 + 4));
            acc[0] = fmaf(f, w0.x, acc[0]);
            acc[1] = fmaf(f, w0.y, acc[1]);
            acc[2] = fmaf(f, w0.z, acc[2]);
            acc[3] = fmaf(f, w0.w, acc[3]);
            acc[4] = fmaf(f, w1.x, acc[4]);
            acc[5] = fmaf(f, w1.y, acc[5]);
            acc[6] = fmaf(f, w1.z, acc[6]);
            acc[7] = fmaf(f, w1.w, acc[7]);
        }

        // relu + store to scratch
        float4 o0, o1;
        o0.x = fmaxf(acc[0], 0.f); o0.y = fmaxf(acc[1], 0.f);
        o0.z = fmaxf(acc[2], 0.f); o0.w = fmaxf(acc[3], 0.f);
        o1.x = fmaxf(acc[4], 0.f); o1.y = fmaxf(acc[5], 0.f);
        o1.z = fmaxf(acc[6], 0.f); o1.w = fmaxf(acc[7], 0.f);
        float4* dst = (float4*)(g_h1 + (size_t)(node0 + n) * D + jg * 8);
        dst[0] = o0;
        dst[1] = o1;

        __syncthreads();   // protect fs/nbs before next tile
    }
}

// ---------------------------------------------------------------------------
// Layer 2 + proj_out, fused, only for the 8192 batch positions:
// h2 = concat(h1[b], max_s h1[neigh[b]]) @ W2 + b2 ; out = h2 @ Wout + bout
// ---------------------------------------------------------------------------
extern "C" __global__ void __launch_bounds__(NTHREADS, 1)
sage_layer2(const int* __restrict__ nidx, const int* __restrict__ batch,
            const float* __restrict__ W2, const float* __restrict__ b2,
            const float* __restrict__ Wout, const float* __restrict__ bout,
            float* __restrict__ out)
{
    extern __shared__ float smem[];
    float* Ws  = smem;                          // W2 [256][128] = 128 KB
    float* Wo  = Ws + 256 * 128;                // Wout [128][64] = 32 KB
    float* fs  = Wo + 128 * 64;                 // [256][FS_STR]
    float* h2s = fs + 256 * FS_STR;             // [128][FS_STR]
    int*   nbs = (int*)(h2s + 128 * FS_STR);    // [TILE][S]
    int*   bid = nbs + TILE * S;                // [TILE]

    const int tid = threadIdx.x;

    // Stage W2 + Wout
    {
        const float4* s2 = (const float4*)W2;
        float4* d2 = (float4*)Ws;
        #pragma unroll
        for (int i = tid; i < 256 * 128 / 4; i += NTHREADS) d2[i] = s2[i];
        const float4* so = (const float4*)Wout;
        float4* do_ = (float4*)Wo;
        #pragma unroll
        for (int i = tid; i < 128 * 64 / 4; i += NTHREADS) do_[i] = so[i];
    }

    const int n  = tid >> 4;
    const int jg = tid & 15;
    float bias2[8];
    #pragma unroll
    for (int u = 0; u < 8; u++) bias2[u] = b2[jg * 8 + u];
    float biaso[4];
    #pragma unroll
    for (int u = 0; u < 4; u++) biaso[u] = bout[jg * 4 + u];

    __syncthreads();

    const int numTiles = NBATCH / TILE;   // 512, exact
    for (int tile = blockIdx.x; tile < numTiles; tile += gridDim.x) {
        const int pos0 = tile * TILE;

        if (tid < TILE) bid[tid] = batch[pos0 + tid];
        __syncthreads();
        {   // neighbor indices of the batch nodes
            const int nn = tid >> 4;      // node 0..15
            const int s  = tid & 15;      // sample 0..15
            nbs[nn * S + s] = nidx[(size_t)bid[nn] * S + s];
        }
        __syncthreads();

        // ---- gather from g_h1 + max ----
        #pragma unroll
        for (int it = 0; it < 2; it++) {
            const int lin = tid + it * NTHREADS;
            const int nn  = lin >> 5;
            const int d4  = lin & 31;
            const float4* hs = (const float4*)(g_h1 + (size_t)bid[nn] * D) + d4;
            float4 self = *hs;
            const int* nb = &nbs[nn * S];
            float4 m = *((const float4*)(g_h1 + (size_t)nb[0] * D) + d4);
            #pragma unroll
            for (int s = 1; s < S; s++) {
                float4 v = *((const float4*)(g_h1 + (size_t)nb[s] * D) + d4);
                m.x = fmaxf(m.x, v.x); m.y = fmaxf(m.y, v.y);
                m.z = fmaxf(m.z, v.z); m.w = fmaxf(m.w, v.w);
            }
            const int d = d4 * 4;
            fs[(d + 0) * FS_STR + nn] = self.x;
            fs[(d + 1) * FS_STR + nn] = self.y;
            fs[(d + 2) * FS_STR + nn] = self.z;
            fs[(d + 3) * FS_STR + nn] = self.w;
            fs[(D + d + 0) * FS_STR + nn] = m.x;
            fs[(D + d + 1) * FS_STR + nn] = m.y;
            fs[(D + d + 2) * FS_STR + nn] = m.z;
            fs[(D + d + 3) * FS_STR + nn] = m.w;
        }
        __syncthreads();

        // ---- GEMM1: h2 (no relu) -> h2s ----
        float acc[8];
        #pragma unroll
        for (int u = 0; u < 8; u++) acc[u] = bias2[u];
        #pragma unroll 8
        for (int k = 0; k < 256; k++) {
            const float f = fs[k * FS_STR + n];
            const float4 w0 = *((const float4*)(Ws + k * 128 + jg * 8));
            const float4 w1 = *((const float4*)(Ws + k * 128 + jg * 8 + 4));
            acc[0] = fmaf(f, w0.x, acc[0]);
            acc[1] = fmaf(f, w0.y, acc[1]);
            acc[2] = fmaf(f, w0.z, acc[2]);
            acc[3] = fmaf(f, w0.w, acc[3]);
            acc[4] = fmaf(f, w1.x, acc[4]);
            acc[5] = fmaf(f, w1.y, acc[5]);
            acc[6] = fmaf(f, w1.z, acc[6]);
            acc[7] = fmaf(f, w1.w, acc[7]);
        }
        #pragma unroll
        for (int u = 0; u < 8; u++) h2s[(jg * 8 + u) * FS_STR + n] = acc[u];
        __syncthreads();

        // ---- GEMM2: out = h2 @ Wout + bout (4 outputs / thread) ----
        float ao[4];
        #pragma unroll
        for (int u = 0; u < 4; u++) ao[u] = biaso[u];
        #pragma unroll 8
        for (int j = 0; j < 128; j++) {
            const float h = h2s[j * FS_STR + n];
            const float4 w = *((const float4*)(Wo + j * 64 + jg * 4));
            ao[0] = fmaf(h, w.x, ao[0]);
            ao[1] = fmaf(h, w.y, ao[1]);
            ao[2] = fmaf(h, w.z, ao[2]);
            ao[3] = fmaf(h, w.w, ao[3]);
        }
        float4 ov = make_float4(ao[0], ao[1], ao[2], ao[3]);
        *((float4*)(out + (size_t)(pos0 + n) * 64 + jg * 4)) = ov;

        __syncthreads();
    }
}

// ---------------------------------------------------------------------------
extern "C" void kernel_launch(void* const* d_in, const int* in_sizes, int n_in,
                              void* d_out, int out_size)
{
    const float* x    = (const float*)d_in[0];
    const int*   nidx = (const int*)  d_in[1];
    const int*   batch= (const int*)  d_in[2];
    const float* W1   = (const float*)d_in[3];
    const float* b1   = (const float*)d_in[4];
    const float* W2   = (const float*)d_in[5];
    const float* b2   = (const float*)d_in[6];
    const float* Wout = (const float*)d_in[7];
    const float* bout = (const float*)d_in[8];
    float* out = (float*)d_out;

    const size_t smem1 = (256 * 128 + 256 * FS_STR) * sizeof(float)
                       + TILE * S * sizeof(int);
    const size_t smem2 = (256 * 128 + 128 * 64 + 256 * FS_STR + 128 * FS_STR) * sizeof(float)
                       + (TILE * S + TILE) * sizeof(int);

    cudaFuncSetAttribute((const void*)sage_layer1,
                         cudaFuncAttributeMaxDynamicSharedMemorySize, (int)smem1);
    cudaFuncSetAttribute((const void*)sage_layer2,
                         cudaFuncAttributeMaxDynamicSharedMemorySize, (int)smem2);

    const int grid = 152;   // GB300: 152 SMs, 1 block/SM (smem-limited)
    sage_layer1<<<grid, NTHREADS, smem1>>>(x, nidx, W1, b1);
    sage_layer2<<<grid, NTHREADS, smem2>>>(nidx, batch, W2, b2, Wout, bout, out);
}

// round 2
// speedup vs baseline: 3.1328x; 3.1328x over previous
#include <cuda_runtime.h>

#define NNODES 100000
#define D      128
#define S      16
#define NBATCH 8192
#define TILE   64
#define FSTR   65          // fs row stride (floats): degree-2 reads, degree-4 writes
#define NT     256

// Layer-1 output scratch (51.2 MB) — __device__ global, allocation-guard legal.
__device__ float g_h1[(size_t)NNODES * D];

// ---------------------------------------------------------------------------
// Layer 1: h1 = relu( concat(x, max_s x[neigh]) @ W1 + b1 )  for ALL nodes.
// TILE=64 nodes per iteration. GEMM thread tile: 4 nodes x 8 outputs.
// ---------------------------------------------------------------------------
extern "C" __global__ void __launch_bounds__(NT, 1)
sage_layer1(const float* __restrict__ x, const int* __restrict__ nidx,
            const float* __restrict__ W1, const float* __restrict__ b1)
{
    extern __shared__ float smem[];
    float* Ws  = smem;                       // [256][128] = 128 KB
    float* fs  = Ws + 256 * 128;             // [256][FSTR]
    int*   nbs = (int*)(fs + 256 * FSTR);    // [TILE][S] = 1024 ints

    const int tid = threadIdx.x;

    // Stage W1 into smem (once per block)
    {
        const float4* src = (const float4*)W1;
        float4* dst = (float4*)Ws;
        for (int i = tid; i < 256 * 128 / 4; i += NT) dst[i] = src[i];
    }

    const int ng = tid & 15;     // node group: nodes ng*4 .. ng*4+3
    const int jg = tid >> 4;     // output group: outs jg*8 .. jg*8+7
    float bias[8];
    {
        float4 b0 = *((const float4*)(b1 + jg * 8));
        float4 b4 = *((const float4*)(b1 + jg * 8 + 4));
        bias[0]=b0.x; bias[1]=b0.y; bias[2]=b0.z; bias[3]=b0.w;
        bias[4]=b4.x; bias[5]=b4.y; bias[6]=b4.z; bias[7]=b4.w;
    }
    __syncthreads();

    const int numTiles = (NNODES + TILE - 1) / TILE;   // 1563
    for (int tile = blockIdx.x; tile < numTiles; tile += gridDim.x) {
        const int node0 = tile * TILE;

        // neighbor indices: 64 nodes x 16 samples
        for (int i = tid; i < TILE * S; i += NT) {
            const int node = node0 + (i >> 4);
            nbs[i] = (node < NNODES) ? nidx[node * S + (i & 15)] : 0;
        }
        __syncthreads();

        // ---- gather + max-aggregate into fs[k][n] ----
        for (int it = 0; it < 8; it++) {
            const int lin = tid + it * NT;      // 0..2047
            const int nn  = lin >> 5;           // node 0..63
            const int d4  = lin & 31;           // float4 group
            int node = node0 + nn;
            if (node >= NNODES) node = 0;
            const float4 self = *((const float4*)(x + (size_t)node * D) + d4);
            const int* nb = &nbs[nn * S];
            float4 m = *((const float4*)(x + (size_t)nb[0] * D) + d4);
            #pragma unroll
            for (int s = 1; s < S; s++) {
                float4 v = *((const float4*)(x + (size_t)nb[s] * D) + d4);
                m.x = fmaxf(m.x, v.x); m.y = fmaxf(m.y, v.y);
                m.z = fmaxf(m.z, v.z); m.w = fmaxf(m.w, v.w);
            }
            const int d = d4 * 4;
            fs[(d + 0) * FSTR + nn] = self.x;
            fs[(d + 1) * FSTR + nn] = self.y;
            fs[(d + 2) * FSTR + nn] = self.z;
            fs[(d + 3) * FSTR + nn] = self.w;
            fs[(D + d + 0) * FSTR + nn] = m.x;
            fs[(D + d + 1) * FSTR + nn] = m.y;
            fs[(D + d + 2) * FSTR + nn] = m.z;
            fs[(D + d + 3) * FSTR + nn] = m.w;
        }
        __syncthreads();

        // ---- register-blocked GEMM: 4 nodes x 8 outputs per thread ----
        float acc[4][8];
        #pragma unroll
        for (int i = 0; i < 4; i++)
            #pragma unroll
            for (int u = 0; u < 8; u++) acc[i][u] = bias[u];

        const float* fb = fs + ng * 4;
        const float* wb = Ws + jg * 8;
        #pragma unroll 4
        for (int k = 0; k < 256; k++) {
            const float f0 = fb[k * FSTR + 0];
            const float f1 = fb[k * FSTR + 1];
            const float f2 = fb[k * FSTR + 2];
            const float f3 = fb[k * FSTR + 3];
            const float4 w0 = *((const float4*)(wb + k * 128));
            const float4 w1 = *((const float4*)(wb + k * 128 + 4));
            float w[8] = {w0.x, w0.y, w0.z, w0.w, w1.x, w1.y, w1.z, w1.w};
            #pragma unroll
            for (int u = 0; u < 8; u++) {
                acc[0][u] = fmaf(f0, w[u], acc[0][u]);
                acc[1][u] = fmaf(f1, w[u], acc[1][u]);
                acc[2][u] = fmaf(f2, w[u], acc[2][u]);
                acc[3][u] = fmaf(f3, w[u], acc[3][u]);
            }
        }

        // relu + store 4 nodes x 8 outs
        #pragma unroll
        for (int i = 0; i < 4; i++) {
            const int node = node0 + ng * 4 + i;
            if (node < NNODES) {
                float4 o0, o1;
                o0.x = fmaxf(acc[i][0], 0.f); o0.y = fmaxf(acc[i][1], 0.f);
                o0.z = fmaxf(acc[i][2], 0.f); o0.w = fmaxf(acc[i][3], 0.f);
                o1.x = fmaxf(acc[i][4], 0.f); o1.y = fmaxf(acc[i][5], 0.f);
                o1.z = fmaxf(acc[i][6], 0.f); o1.w = fmaxf(acc[i][7], 0.f);
                float4* dst = (float4*)(g_h1 + (size_t)node * D + jg * 8);
                dst[0] = o0; dst[1] = o1;
            }
        }
        __syncthreads();
    }
}

// ---------------------------------------------------------------------------
// Layer 2 + proj_out (batch nodes only):
// h2 = concat(h1[b], max_s h1[neigh[b]]) @ W2 + b2 ; out = h2 @ Wout + bout
// Smem: W2 (128K) + fs (66K). h2 and Wout reuse the fs region after GEMM1.
// ---------------------------------------------------------------------------
extern "C" __global__ void __launch_bounds__(NT, 1)
sage_layer2(const float* __restrict__ x_unused, const int* __restrict__ nidx,
            const int* __restrict__ batch,
            const float* __restrict__ W2, const float* __restrict__ b2,
            const float* __restrict__ Wout, const float* __restrict__ bout,
            float* __restrict__ out)
{
    extern __shared__ float smem[];
    float* Ws  = smem;                       // W2 [256][128]
    float* fs  = Ws + 256 * 128;             // [256][FSTR]; later: h2s[128][FSTR] + Wo
    int*   nbs = (int*)(fs + 256 * FSTR);    // [TILE][S]
    float* h2s = fs;                         // [128][FSTR] (reuses fs after GEMM1)
    float* Wo  = fs + 128 * FSTR;            // [128][64] staged after GEMM1

    const int tid = threadIdx.x;

    {
        const float4* src = (const float4*)W2;
        float4* dst = (float4*)Ws;
        for (int i = tid; i < 256 * 128 / 4; i += NT) dst[i] = src[i];
    }

    const int ng = tid & 15;
    const int jg = tid >> 4;
    float bias2[8];
    {
        float4 b0 = *((const float4*)(b2 + jg * 8));
        float4 b4 = *((const float4*)(b2 + jg * 8 + 4));
        bias2[0]=b0.x; bias2[1]=b0.y; bias2[2]=b0.z; bias2[3]=b0.w;
        bias2[4]=b4.x; bias2[5]=b4.y; bias2[6]=b4.z; bias2[7]=b4.w;
    }
    const int og = tid >> 4;   // GEMM2: 4 outs per thread
    float biaso[4];
    {
        float4 bo = *((const float4*)(bout + og * 4));
        biaso[0]=bo.x; biaso[1]=bo.y; biaso[2]=bo.z; biaso[3]=bo.w;
    }
    __syncthreads();

    const int numTiles = NBATCH / TILE;   // 128, exact
    for (int tile = blockIdx.x; tile < numTiles; tile += gridDim.x) {
        const int pos0 = tile * TILE;

        // neighbor indices of the batch nodes (batch read direct, L1-cached)
        for (int i = tid; i < TILE * S; i += NT) {
            const int bnode = __ldg(batch + pos0 + (i >> 4));
            nbs[i] = nidx[(size_t)bnode * S + (i & 15)];
        }
        __syncthreads();

        // ---- gather from g_h1 + max ----
        for (int it = 0; it < 8; it++) {
            const int lin = tid + it * NT;
            const int nn  = lin >> 5;
            const int d4  = lin & 31;
            const int bnode = __ldg(batch + pos0 + nn);
            const float4 self = *((const float4*)(g_h1 + (size_t)bnode * D) + d4);
            const int* nb = &nbs[nn * S];
            float4 m = *((const float4*)(g_h1 + (size_t)nb[0] * D) + d4);
            #pragma unroll
            for (int s = 1; s < S; s++) {
                float4 v = *((const float4*)(g_h1 + (size_t)nb[s] * D) + d4);
                m.x = fmaxf(m.x, v.x); m.y = fmaxf(m.y, v.y);
                m.z = fmaxf(m.z, v.z); m.w = fmaxf(m.w, v.w);
            }
            const int d = d4 * 4;
            fs[(d + 0) * FSTR + nn] = self.x;
            fs[(d + 1) * FSTR + nn] = self.y;
            fs[(d + 2) * FSTR + nn] = self.z;
            fs[(d + 3) * FSTR + nn] = self.w;
            fs[(D + d + 0) * FSTR + nn] = m.x;
            fs[(D + d + 1) * FSTR + nn] = m.y;
            fs[(D + d + 2) * FSTR + nn] = m.z;
            fs[(D + d + 3) * FSTR + nn] = m.w;
        }
        __syncthreads();

        // ---- GEMM1: h2 (no relu), register tile 4 nodes x 8 outs ----
        float acc[4][8];
        #pragma unroll
        for (int i = 0; i < 4; i++)
            #pragma unroll
            for (int u = 0; u < 8; u++) acc[i][u] = bias2[u];

        const float* fb = fs + ng * 4;
        const float* wb = Ws + jg * 8;
        #pragma unroll 4
        for (int k = 0; k < 256; k++) {
            const float f0 = fb[k * FSTR + 0];
            const float f1 = fb[k * FSTR + 1];
            const float f2 = fb[k * FSTR + 2];
            const float f3 = fb[k * FSTR + 3];
            const float4 w0 = *((const float4*)(wb + k * 128));
            const float4 w1 = *((const float4*)(wb + k * 128 + 4));
            float w[8] = {w0.x, w0.y, w0.z, w0.w, w1.x, w1.y, w1.z, w1.w};
            #pragma unroll
            for (int u = 0; u < 8; u++) {
                acc[0][u] = fmaf(f0, w[u], acc[0][u]);
                acc[1][u] = fmaf(f1, w[u], acc[1][u]);
                acc[2][u] = fmaf(f2, w[u], acc[2][u]);
                acc[3][u] = fmaf(f3, w[u], acc[3][u]);
            }
        }
        __syncthreads();   // fs reads done; safe to overwrite with h2s / Wo

        // write h2 into h2s (reuses fs low region) + stage Wout into fs high region
        #pragma unroll
        for (int u = 0; u < 8; u++) {
            #pragma unroll
            for (int i = 0; i < 4; i++)
                h2s[(jg * 8 + u) * FSTR + ng * 4 + i] = acc[i][u];
        }
        {
            const float4* src = (const float4*)Wout;
            float4* dst = (float4*)Wo;
            for (int i = tid; i < 128 * 64 / 4; i += NT) dst[i] = src[i];
        }
        __syncthreads();

        // ---- GEMM2: out = h2 @ Wout + bout (4 nodes x 4 outs / thread) ----
        float ao[4][4];
        #pragma unroll
        for (int i = 0; i < 4; i++)
            #pragma unroll
            for (int u = 0; u < 4; u++) ao[i][u] = biaso[u];

        const float* hb = h2s + ng * 4;
        #pragma unroll 4
        for (int j = 0; j < 128; j++) {
            const float h0 = hb[j * FSTR + 0];
            const float h1v = hb[j * FSTR + 1];
            const float h2v = hb[j * FSTR + 2];
            const float h3 = hb[j * FSTR + 3];
            const float4 w = *((const float4*)(Wo + j * 64 + og * 4));
            const float wv[4] = {w.x, w.y, w.z, w.w};
            #pragma unroll
            for (int u = 0; u < 4; u++) {
                ao[0][u] = fmaf(h0,  wv[u], ao[0][u]);
                ao[1][u] = fmaf(h1v, wv[u], ao[1][u]);
                ao[2][u] = fmaf(h2v, wv[u], ao[2][u]);
                ao[3][u] = fmaf(h3,  wv[u], ao[3][u]);
            }
        }
        #pragma unroll
        for (int i = 0; i < 4; i++) {
            float4 ov = make_float4(ao[i][0], ao[i][1], ao[i][2], ao[i][3]);
            *((float4*)(out + (size_t)(pos0 + ng * 4 + i) * 64 + og * 4)) = ov;
        }
        __syncthreads();
    }
}

// ---------------------------------------------------------------------------
extern "C" void kernel_launch(void* const* d_in, const int* in_sizes, int n_in,
                              void* d_out, int out_size)
{
    const float* x    = (const float*)d_in[0];
    const int*   nidx = (const int*)  d_in[1];
    const int*   batch= (const int*)  d_in[2];
    const float* W1   = (const float*)d_in[3];
    const float* b1   = (const float*)d_in[4];
    const float* W2   = (const float*)d_in[5];
    const float* b2   = (const float*)d_in[6];
    const float* Wout = (const float*)d_in[7];
    const float* bout = (const float*)d_in[8];
    float* out = (float*)d_out;

    const size_t smem1 = (256 * 128 + 256 * FSTR) * sizeof(float)
                       + TILE * S * sizeof(int);
    const size_t smem2 = smem1;   // same layout (fs region reused for h2s/Wo)

    cudaFuncSetAttribute((const void*)sage_layer1,
                         cudaFuncAttributeMaxDynamicSharedMemorySize, (int)smem1);
    cudaFuncSetAttribute((const void*)sage_layer2,
                         cudaFuncAttributeMaxDynamicSharedMemorySize, (int)smem2);

    sage_layer1<<<152, NT, smem1>>>(x, nidx, W1, b1);
    sage_layer2<<<128, NT, smem2>>>(x, nidx, batch, W2, b2, Wout, bout, out);
}

// round 4
// speedup vs baseline: 3.3098x; 1.0565x over previous
#include <cuda_runtime.h>
#include <cstdint>

#define NNODES 100000
#define D      128
#define S      16
#define NBATCH 8192
#define TILE   64
#define FSTR   65          // fs row stride (floats): degree-2 reads, degree-4 writes
#define NT     256

typedef unsigned long long ull;

// Layer-1 output scratch (51.2 MB) — __device__ global, allocation-guard legal.
__device__ float g_h1[(size_t)NNODES * D];

// ---------------- packed f32x2 helpers (Blackwell FFMA2) ----------------
__device__ __forceinline__ ull fma2(ull a, ull b, ull c) {
    ull d;
    asm("fma.rn.f32x2 %0, %1, %2, %3;" : "=l"(d) : "l"(a), "l"(b), "l"(c));
    return d;
}
__device__ __forceinline__ ull pk2(float lo, float hi) {
    ull r;
    asm("mov.b64 %0, {%1, %2};" : "=l"(r) : "f"(lo), "f"(hi));
    return r;
}
__device__ __forceinline__ ull dup2(float f) { return pk2(f, f); }
__device__ __forceinline__ float2 unpk(ull v) {
    float lo, hi;
    asm("mov.b64 {%0, %1}, %2;" : "=f"(lo), "=f"(hi) : "l"(v));
    return make_float2(lo, hi);
}

// ---------------------------------------------------------------------------
// Layer 1: h1 = relu( concat(x, max_s x[neigh]) @ W1 + b1 )  for ALL nodes.
// TILE=64 nodes/iter. GEMM thread tile: 4 nodes x 8 outputs, FFMA2-packed.
// ---------------------------------------------------------------------------
extern "C" __global__ void __launch_bounds__(NT, 1)
sage_layer1(const float* __restrict__ x, const int* __restrict__ nidx,
            const float* __restrict__ W1, const float* __restrict__ b1)
{
    extern __shared__ float smem[];
    float* Ws  = smem;                       // [256][128] = 128 KB
    float* fs  = Ws + 256 * 128;             // [256][FSTR]
    int*   nbs = (int*)(fs + 256 * FSTR);    // [TILE][S]

    const int tid = threadIdx.x;

    {   // stage W1
        const float4* src = (const float4*)W1;
        float4* dst = (float4*)Ws;
        for (int i = tid; i < 256 * 128 / 4; i += NT) dst[i] = src[i];
    }

    const int ng = tid & 15;     // node group: nodes ng*4 .. ng*4+3
    const int jg = tid >> 4;     // output group: outs jg*8 .. jg*8+7
    ull bias[4];                 // 8 outputs as 4 packed pairs
    {
        float4 b0 = *((const float4*)(b1 + jg * 8));
        float4 b4 = *((const float4*)(b1 + jg * 8 + 4));
        bias[0] = pk2(b0.x, b0.y); bias[1] = pk2(b0.z, b0.w);
        bias[2] = pk2(b4.x, b4.y); bias[3] = pk2(b4.z, b4.w);
    }
    __syncthreads();

    const int numTiles = (NNODES + TILE - 1) / TILE;   // 1563
    for (int tile = blockIdx.x; tile < numTiles; tile += gridDim.x) {
        const int node0 = tile * TILE;

        for (int i = tid; i < TILE * S; i += NT) {
            const int node = node0 + (i >> 4);
            nbs[i] = (node < NNODES) ? nidx[node * S + (i & 15)] : 0;
        }
        __syncthreads();

        // ---- gather + max-aggregate into fs[k][n] ----
        for (int it = 0; it < 8; it++) {
            const int lin = tid + it * NT;      // 0..2047
            const int nn  = lin >> 5;           // node 0..63
            const int d4  = lin & 31;           // float4 group
            int node = node0 + nn;
            if (node >= NNODES) node = 0;
            const float4 self = *((const float4*)(x + (size_t)node * D) + d4);
            const int* nb = &nbs[nn * S];
            float4 m = *((const float4*)(x + (size_t)nb[0] * D) + d4);
            #pragma unroll
            for (int s = 1; s < S; s++) {
                float4 v = *((const float4*)(x + (size_t)nb[s] * D) + d4);
                m.x = fmaxf(m.x, v.x); m.y = fmaxf(m.y, v.y);
                m.z = fmaxf(m.z, v.z); m.w = fmaxf(m.w, v.w);
            }
            const int d = d4 * 4;
            fs[(d + 0) * FSTR + nn] = self.x;
            fs[(d + 1) * FSTR + nn] = self.y;
            fs[(d + 2) * FSTR + nn] = self.z;
            fs[(d + 3) * FSTR + nn] = self.w;
            fs[(D + d + 0) * FSTR + nn] = m.x;
            fs[(D + d + 1) * FSTR + nn] = m.y;
            fs[(D + d + 2) * FSTR + nn] = m.z;
            fs[(D + d + 3) * FSTR + nn] = m.w;
        }
        __syncthreads();

        // ---- FFMA2 GEMM: 4 nodes x 8 outputs (4 packed pairs) per thread ----
        ull acc[4][4];
        #pragma unroll
        for (int i = 0; i < 4; i++)
            #pragma unroll
            for (int u = 0; u < 4; u++) acc[i][u] = bias[u];

        const float* fb = fs + ng * 4;
        const float* wb = Ws + jg * 8;
        #pragma unroll 4
        for (int k = 0; k < 256; k++) {
            const float f0 = fb[k * FSTR + 0];
            const float f1 = fb[k * FSTR + 1];
            const float f2 = fb[k * FSTR + 2];
            const float f3 = fb[k * FSTR + 3];
            const ulonglong2 wa = *((const ulonglong2*)(wb + k * 128));
            const ulonglong2 wc = *((const ulonglong2*)(wb + k * 128 + 4));
            const ull w[4] = {wa.x, wa.y, wc.x, wc.y};
            const ull F0 = dup2(f0), F1 = dup2(f1), F2 = dup2(f2), F3 = dup2(f3);
            #pragma unroll
            for (int u = 0; u < 4; u++) {
                acc[0][u] = fma2(F0, w[u], acc[0][u]);
                acc[1][u] = fma2(F1, w[u], acc[1][u]);
                acc[2][u] = fma2(F2, w[u], acc[2][u]);
                acc[3][u] = fma2(F3, w[u], acc[3][u]);
            }
        }

        // relu + store 4 nodes x 8 outs
        #pragma unroll
        for (int i = 0; i < 4; i++) {
            const int node = node0 + ng * 4 + i;
            if (node < NNODES) {
                const float2 p0 = unpk(acc[i][0]);
                const float2 p1 = unpk(acc[i][1]);
                const float2 p2 = unpk(acc[i][2]);
                const float2 p3 = unpk(acc[i][3]);
                float4 o0, o1;
                o0.x = fmaxf(p0.x, 0.f); o0.y = fmaxf(p0.y, 0.f);
                o0.z = fmaxf(p1.x, 0.f); o0.w = fmaxf(p1.y, 0.f);
                o1.x = fmaxf(p2.x, 0.f); o1.y = fmaxf(p2.y, 0.f);
                o1.z = fmaxf(p3.x, 0.f); o1.w = fmaxf(p3.y, 0.f);
                float4* dst = (float4*)(g_h1 + (size_t)node * D + jg * 8);
                dst[0] = o0; dst[1] = o1;
            }
        }
        __syncthreads();
    }
}

// ---------------------------------------------------------------------------
// Layer 2 + proj_out (batch nodes only), FFMA2-packed GEMMs.
// ---------------------------------------------------------------------------
extern "C" __global__ void __launch_bounds__(NT, 1)
sage_layer2(const int* __restrict__ nidx, const int* __restrict__ batch,
            const float* __restrict__ W2, const float* __restrict__ b2,
            const float* __restrict__ Wout, const float* __restrict__ bout,
            float* __restrict__ out)
{
    extern __shared__ float smem[];
    float* Ws  = smem;                       // W2 [256][128]
    float* fs  = Ws + 256 * 128;             // [256][FSTR]
    int*   nbs = (int*)(fs + 256 * FSTR);    // [TILE][S]
    float* h2s = fs;                         // reuses fs after GEMM1
    float* Wo  = fs + 128 * FSTR;            // [128][64] staged after GEMM1

    const int tid = threadIdx.x;

    {
        const float4* src = (const float4*)W2;
        float4* dst = (float4*)Ws;
        for (int i = tid; i < 256 * 128 / 4; i += NT) dst[i] = src[i];
    }

    const int ng = tid & 15;
    const int jg = tid >> 4;
    ull bias2[4];
    {
        float4 b0 = *((const float4*)(b2 + jg * 8));
        float4 b4 = *((const float4*)(b2 + jg * 8 + 4));
        bias2[0] = pk2(b0.x, b0.y); bias2[1] = pk2(b0.z, b0.w);
        bias2[2] = pk2(b4.x, b4.y); bias2[3] = pk2(b4.z, b4.w);
    }
    const int og = tid >> 4;   // GEMM2: 4 outs per thread
    ull biaso[2];
    {
        float4 bo = *((const float4*)(bout + og * 4));
        biaso[0] = pk2(bo.x, bo.y); biaso[1] = pk2(bo.z, bo.w);
    }
    __syncthreads();

    const int numTiles = NBATCH / TILE;   // 128
    for (int tile = blockIdx.x; tile < numTiles; tile += gridDim.x) {
        const int pos0 = tile * TILE;

        for (int i = tid; i < TILE * S; i += NT) {
            const int bnode = __ldg(batch + pos0 + (i >> 4));
            nbs[i] = nidx[(size_t)bnode * S + (i & 15)];
        }
        __syncthreads();

        for (int it = 0; it < 8; it++) {
            const int lin = tid + it * NT;
            const int nn  = lin >> 5;
            const int d4  = lin & 31;
            const int bnode = __ldg(batch + pos0 + nn);
            const float4 self = *((const float4*)(g_h1 + (size_t)bnode * D) + d4);
            const int* nb = &nbs[nn * S];
            float4 m = *((const float4*)(g_h1 + (size_t)nb[0] * D) + d4);
            #pragma unroll
            for (int s = 1; s < S; s++) {
                float4 v = *((const float4*)(g_h1 + (size_t)nb[s] * D) + d4);
                m.x = fmaxf(m.x, v.x); m.y = fmaxf(m.y, v.y);
                m.z = fmaxf(m.z, v.z); m.w = fmaxf(m.w, v.w);
            }
            const int d = d4 * 4;
            fs[(d + 0) * FSTR + nn] = self.x;
            fs[(d + 1) * FSTR + nn] = self.y;
            fs[(d + 2) * FSTR + nn] = self.z;
            fs[(d + 3) * FSTR + nn] = self.w;
            fs[(D + d + 0) * FSTR + nn] = m.x;
            fs[(D + d + 1) * FSTR + nn] = m.y;
            fs[(D + d + 2) * FSTR + nn] = m.z;
            fs[(D + d + 3) * FSTR + nn] = m.w;
        }
        __syncthreads();

        // ---- GEMM1 (FFMA2): h2, 4 nodes x 8 outs ----
        ull acc[4][4];
        #pragma unroll
        for (int i = 0; i < 4; i++)
            #pragma unroll
            for (int u = 0; u < 4; u++) acc[i][u] = bias2[u];

        const float* fb = fs + ng * 4;
        const float* wb = Ws + jg * 8;
        #pragma unroll 4
        for (int k = 0; k < 256; k++) {
            const float f0 = fb[k * FSTR + 0];
            const float f1 = fb[k * FSTR + 1];
            const float f2 = fb[k * FSTR + 2];
            const float f3 = fb[k * FSTR + 3];
            const ulonglong2 wa = *((const ulonglong2*)(wb + k * 128));
            const ulonglong2 wc = *((const ulonglong2*)(wb + k * 128 + 4));
            const ull w[4] = {wa.x, wa.y, wc.x, wc.y};
            const ull F0 = dup2(f0), F1 = dup2(f1), F2 = dup2(f2), F3 = dup2(f3);
            #pragma unroll
            for (int u = 0; u < 4; u++) {
                acc[0][u] = fma2(F0, w[u], acc[0][u]);
                acc[1][u] = fma2(F1, w[u], acc[1][u]);
                acc[2][u] = fma2(F2, w[u], acc[2][u]);
                acc[3][u] = fma2(F3, w[u], acc[3][u]);
            }
        }
        __syncthreads();   // fs reads done; safe to overwrite with h2s / Wo

        #pragma unroll
        for (int i = 0; i < 4; i++) {
            const float2 p0 = unpk(acc[i][0]);
            const float2 p1 = unpk(acc[i][1]);
            const float2 p2 = unpk(acc[i][2]);
            const float2 p3 = unpk(acc[i][3]);
            h2s[(jg * 8 + 0) * FSTR + ng * 4 + i] = p0.x;
            h2s[(jg * 8 + 1) * FSTR + ng * 4 + i] = p0.y;
            h2s[(jg * 8 + 2) * FSTR + ng * 4 + i] = p1.x;
            h2s[(jg * 8 + 3) * FSTR + ng * 4 + i] = p1.y;
            h2s[(jg * 8 + 4) * FSTR + ng * 4 + i] = p2.x;
            h2s[(jg * 8 + 5) * FSTR + ng * 4 + i] = p2.y;
            h2s[(jg * 8 + 6) * FSTR + ng * 4 + i] = p3.x;
            h2s[(jg * 8 + 7) * FSTR + ng * 4 + i] = p3.y;
        }
        {
            const float4* src = (const float4*)Wout;
            float4* dst = (float4*)Wo;
            for (int i = tid; i < 128 * 64 / 4; i += NT) dst[i] = src[i];
        }
        __syncthreads();

        // ---- GEMM2 (FFMA2): out = h2 @ Wout + bout, 4 nodes x 4 outs ----
        ull ao[4][2];
        #pragma unroll
        for (int i = 0; i < 4; i++) {
            ao[i][0] = biaso[0]; ao[i][1] = biaso[1];
        }

        const float* hb = h2s + ng * 4;
        #pragma unroll 4
        for (int j = 0; j < 128; j++) {
            const float h0  = hb[j * FSTR + 0];
            const float h1v = hb[j * FSTR + 1];
            const float h2v = hb[j * FSTR + 2];
            const float h3  = hb[j * FSTR + 3];
            const ulonglong2 wv = *((const ulonglong2*)(Wo + j * 64 + og * 4));
            const ull H0 = dup2(h0), H1 = dup2(h1v), H2 = dup2(h2v), H3 = dup2(h3);
            ao[0][0] = fma2(H0, wv.x, ao[0][0]); ao[0][1] = fma2(H0, wv.y, ao[0][1]);
            ao[1][0] = fma2(H1, wv.x, ao[1][0]); ao[1][1] = fma2(H1, wv.y, ao[1][1]);
            ao[2][0] = fma2(H2, wv.x, ao[2][0]); ao[2][1] = fma2(H2, wv.y, ao[2][1]);
            ao[3][0] = fma2(H3, wv.x, ao[3][0]); ao[3][1] = fma2(H3, wv.y, ao[3][1]);
        }
        #pragma unroll
        for (int i = 0; i < 4; i++) {
            const float2 q0 = unpk(ao[i][0]);
            const float2 q1 = unpk(ao[i][1]);
            float4 ov = make_float4(q0.x, q0.y, q1.x, q1.y);
            *((float4*)(out + (size_t)(pos0 + ng * 4 + i) * 64 + og * 4)) = ov;
        }
        __syncthreads();
    }
}

// ---------------------------------------------------------------------------
extern "C" void kernel_launch(void* const* d_in, const int* in_sizes, int n_in,
                              void* d_out, int out_size)
{
    const float* x    = (const float*)d_in[0];
    const int*   nidx = (const int*)  d_in[1];
    const int*   batch= (const int*)  d_in[2];
    const float* W1   = (const float*)d_in[3];
    const float* b1   = (const float*)d_in[4];
    const float* W2   = (const float*)d_in[5];
    const float* b2   = (const float*)d_in[6];
    const float* Wout = (const float*)d_in[7];
    const float* bout = (const float*)d_in[8];
    float* out = (float*)d_out;

    const size_t smem1 = (256 * 128 + 256 * FSTR) * sizeof(float)
                       + TILE * S * sizeof(int);
    const size_t smem2 = smem1;

    cudaFuncSetAttribute((const void*)sage_layer1,
                         cudaFuncAttributeMaxDynamicSharedMemorySize, (int)smem1);
    cudaFuncSetAttribute((const void*)sage_layer2,
                         cudaFuncAttributeMaxDynamicSharedMemorySize, (int)smem2);

    sage_layer1<<<152, NT, smem1>>>(x, nidx, W1, b1);
    sage_layer2<<<128, NT, smem2>>>(nidx, batch, W2, b2, Wout, bout, out);
}

// round 5
// speedup vs baseline: 3.9326x; 1.1882x over previous
#include <cuda_runtime.h>
#include <cstdint>

#define NNODES 100000
#define D      128
#define S      16
#define NBATCH 8192
#define NT     256

typedef unsigned long long ull;

// ---- layer-1 warp-specialized config ----
#define TILE1  32                  // nodes per tile (100000/32 = 3125 exact)
#define NTILES1 (NNODES / TILE1)
#define FSTR1  33                  // fs row stride (floats)
#define FS_FLOATS (256 * FSTR1)    // 8448 floats per buffer

// ---- layer-2 (round-4 proven) config ----
#define TILE2  64
#define FSTR   65

// Layer-1 output scratch (51.2 MB)
__device__ float g_h1[(size_t)NNODES * D];

// ---------------- packed f32x2 helpers (Blackwell FFMA2) ----------------
__device__ __forceinline__ ull fma2(ull a, ull b, ull c) {
    ull d;
    asm("fma.rn.f32x2 %0, %1, %2, %3;" : "=l"(d) : "l"(a), "l"(b), "l"(c));
    return d;
}
__device__ __forceinline__ ull pk2(float lo, float hi) {
    ull r;
    asm("mov.b64 %0, {%1, %2};" : "=l"(r) : "f"(lo), "f"(hi));
    return r;
}
__device__ __forceinline__ ull dup2(float f) { return pk2(f, f); }
__device__ __forceinline__ float2 unpk(ull v) {
    float lo, hi;
    asm("mov.b64 {%0, %1}, %2;" : "=f"(lo), "=f"(hi) : "l"(v));
    return make_float2(lo, hi);
}

#define BAR_SYNC(id)   asm volatile("bar.sync %0, 256;"   :: "r"(id) : "memory")
#define BAR_ARRIVE(id) asm volatile("bar.arrive %0, 256;" :: "r"(id) : "memory")

// ---------------------------------------------------------------------------
// Layer 1: warp-specialized producer(gather) / consumer(FFMA2 GEMM) pipeline.
// h1 = relu( concat(x, max_s x[neigh]) @ W1 + b1 ) for ALL nodes.
// ---------------------------------------------------------------------------
extern "C" __global__ void __launch_bounds__(NT, 1)
sage_layer1(const float* __restrict__ x, const int* __restrict__ nidx,
            const float* __restrict__ W1, const float* __restrict__ b1)
{
    extern __shared__ float smem[];
    float* Ws = smem;                      // [256][128] = 128 KB
    float* fs = Ws + 256 * 128;            // 2 buffers of [256][FSTR1]

    const int tid = threadIdx.x;

    {   // stage W1 (all threads)
        const float4* src = (const float4*)W1;
        float4* dst = (float4*)Ws;
        for (int i = tid; i < 256 * 128 / 4; i += NT) dst[i] = src[i];
    }
    __syncthreads();

    if (tid < 128) {
        // ================= PRODUCER (warps 0-3) =================
        const int ptid = tid;
        for (int i = 0, tile = blockIdx.x; tile < NTILES1; tile += gridDim.x, i++) {
            const int b = i & 1;
            if (i >= 2) BAR_SYNC(3 + b);             // wait: consumer done with buf b
            float* fsb = fs + b * FS_FLOATS;
            const int node0 = tile * TILE1;

            #pragma unroll 2
            for (int it = 0; it < 8; it++) {
                const int lin = ptid + it * 128;     // 0..1023
                const int nn  = lin >> 5;            // node 0..31 (warp-uniform)
                const int d4  = lin & 31;            // float4 group = lane
                const int node = node0 + nn;

                // neighbor indices: warp-uniform addresses -> broadcast loads
                const int4* np = (const int4*)(nidx + (size_t)node * S);
                const int4 na = np[0], nb4 = np[1], nc = np[2], nd = np[3];
                const int nb[16] = {na.x, na.y, na.z, na.w,
                                    nb4.x, nb4.y, nb4.z, nb4.w,
                                    nc.x, nc.y, nc.z, nc.w,
                                    nd.x, nd.y, nd.z, nd.w};

                const float4 self = *((const float4*)(x + (size_t)node * D) + d4);
                float4 m = *((const float4*)(x + (size_t)nb[0] * D) + d4);
                #pragma unroll
                for (int s = 1; s < S; s++) {
                    float4 v = *((const float4*)(x + (size_t)nb[s] * D) + d4);
                    m.x = fmaxf(m.x, v.x); m.y = fmaxf(m.y, v.y);
                    m.z = fmaxf(m.z, v.z); m.w = fmaxf(m.w, v.w);
                }
                const int d = d4 * 4;
                fsb[(d + 0) * FSTR1 + nn] = self.x;
                fsb[(d + 1) * FSTR1 + nn] = self.y;
                fsb[(d + 2) * FSTR1 + nn] = self.z;
                fsb[(d + 3) * FSTR1 + nn] = self.w;
                fsb[(D + d + 0) * FSTR1 + nn] = m.x;
                fsb[(D + d + 1) * FSTR1 + nn] = m.y;
                fsb[(D + d + 2) * FSTR1 + nn] = m.z;
                fsb[(D + d + 3) * FSTR1 + nn] = m.w;
            }
            BAR_ARRIVE(1 + b);                       // signal: buf b full
        }
    } else {
        // ================= CONSUMER (warps 4-7) =================
        const int ctid = tid - 128;
        const int og = ctid >> 3;       // output group: outs og*8..og*8+7 (0..15)
        const int ng = ctid & 7;        // node group: nodes ng*4..ng*4+3 (0..7)
        ull bias[4];
        {
            float4 b0 = *((const float4*)(b1 + og * 8));
            float4 b4 = *((const float4*)(b1 + og * 8 + 4));
            bias[0] = pk2(b0.x, b0.y); bias[1] = pk2(b0.z, b0.w);
            bias[2] = pk2(b4.x, b4.y); bias[3] = pk2(b4.z, b4.w);
        }
        const float* wb = Ws + og * 8;

        for (int i = 0, tile = blockIdx.x; tile < NTILES1; tile += gridDim.x, i++) {
            const int b = i & 1;
            BAR_SYNC(1 + b);                         // wait: buf b full
            const float* fsb = fs + b * FS_FLOATS;
            const int node0 = tile * TILE1;

            ull acc[4][4];
            #pragma unroll
            for (int r = 0; r < 4; r++)
                #pragma unroll
                for (int u = 0; u < 4; u++) acc[r][u] = bias[u];

            const float* fb = fsb + ng * 4;
            #pragma unroll 4
            for (int k = 0; k < 256; k++) {
                const float f0 = fb[k * FSTR1 + 0];
                const float f1 = fb[k * FSTR1 + 1];
                const float f2 = fb[k * FSTR1 + 2];
                const float f3 = fb[k * FSTR1 + 3];
                const ulonglong2 wa = *((const ulonglong2*)(wb + k * 128));
                const ulonglong2 wc = *((const ulonglong2*)(wb + k * 128 + 4));
                const ull w[4] = {wa.x, wa.y, wc.x, wc.y};
                const ull F0 = dup2(f0), F1 = dup2(f1), F2 = dup2(f2), F3 = dup2(f3);
                #pragma unroll
                for (int u = 0; u < 4; u++) {
                    acc[0][u] = fma2(F0, w[u], acc[0][u]);
                    acc[1][u] = fma2(F1, w[u], acc[1][u]);
                    acc[2][u] = fma2(F2, w[u], acc[2][u]);
                    acc[3][u] = fma2(F3, w[u], acc[3][u]);
                }
            }
            BAR_ARRIVE(3 + b);                       // signal: buf b free

            // relu + STG 4 nodes x 8 outs
            #pragma unroll
            for (int r = 0; r < 4; r++) {
                const int node = node0 + ng * 4 + r;
                const float2 p0 = unpk(acc[r][0]);
                const float2 p1 = unpk(acc[r][1]);
                const float2 p2 = unpk(acc[r][2]);
                const float2 p3 = unpk(acc[r][3]);
                float4 o0, o1;
                o0.x = fmaxf(p0.x, 0.f); o0.y = fmaxf(p0.y, 0.f);
                o0.z = fmaxf(p1.x, 0.f); o0.w = fmaxf(p1.y, 0.f);
                o1.x = fmaxf(p2.x, 0.f); o1.y = fmaxf(p2.y, 0.f);
                o1.z = fmaxf(p3.x, 0.f); o1.w = fmaxf(p3.y, 0.f);
                float4* dst = (float4*)(g_h1 + (size_t)node * D + og * 8);
                dst[0] = o0; dst[1] = o1;
            }
        }
    }
}

// ---------------------------------------------------------------------------
// Layer 2 + proj_out (batch nodes only), FFMA2-packed GEMMs (round-4 proven).
// ---------------------------------------------------------------------------
extern "C" __global__ void __launch_bounds__(NT, 1)
sage_layer2(const int* __restrict__ nidx, const int* __restrict__ batch,
            const float* __restrict__ W2, const float* __restrict__ b2,
            const float* __restrict__ Wout, const float* __restrict__ bout,
            float* __restrict__ out)
{
    extern __shared__ float smem[];
    float* Ws  = smem;                       // W2 [256][128]
    float* fs  = Ws + 256 * 128;             // [256][FSTR]
    int*   nbs = (int*)(fs + 256 * FSTR);    // [TILE2][S]
    float* h2s = fs;                         // reuses fs after GEMM1
    float* Wo  = fs + 128 * FSTR;            // [128][64] staged after GEMM1

    const int tid = threadIdx.x;

    {
        const float4* src = (const float4*)W2;
        float4* dst = (float4*)Ws;
        for (int i = tid; i < 256 * 128 / 4; i += NT) dst[i] = src[i];
    }

    const int ng = tid & 15;
    const int jg = tid >> 4;
    ull bias2[4];
    {
        float4 b0 = *((const float4*)(b2 + jg * 8));
        float4 b4 = *((const float4*)(b2 + jg * 8 + 4));
        bias2[0] = pk2(b0.x, b0.y); bias2[1] = pk2(b0.z, b0.w);
        bias2[2] = pk2(b4.x, b4.y); bias2[3] = pk2(b4.z, b4.w);
    }
    const int og = tid >> 4;
    ull biaso[2];
    {
        float4 bo = *((const float4*)(bout + og * 4));
        biaso[0] = pk2(bo.x, bo.y); biaso[1] = pk2(bo.z, bo.w);
    }
    __syncthreads();

    const int numTiles = NBATCH / TILE2;   // 128
    for (int tile = blockIdx.x; tile < numTiles; tile += gridDim.x) {
        const int pos0 = tile * TILE2;

        for (int i = tid; i < TILE2 * S; i += NT) {
            const int bnode = __ldg(batch + pos0 + (i >> 4));
            nbs[i] = nidx[(size_t)bnode * S + (i & 15)];
        }
        __syncthreads();

        for (int it = 0; it < 8; it++) {
            const int lin = tid + it * NT;
            const int nn  = lin >> 5;
            const int d4  = lin & 31;
            const int bnode = __ldg(batch + pos0 + nn);
            const float4 self = *((const float4*)(g_h1 + (size_t)bnode * D) + d4);
            const int* nb = &nbs[nn * S];
            float4 m = *((const float4*)(g_h1 + (size_t)nb[0] * D) + d4);
            #pragma unroll
            for (int s = 1; s < S; s++) {
                float4 v = *((const float4*)(g_h1 + (size_t)nb[s] * D) + d4);
                m.x = fmaxf(m.x, v.x); m.y = fmaxf(m.y, v.y);
                m.z = fmaxf(m.z, v.z); m.w = fmaxf(m.w, v.w);
            }
            const int d = d4 * 4;
            fs[(d + 0) * FSTR + nn] = self.x;
            fs[(d + 1) * FSTR + nn] = self.y;
            fs[(d + 2) * FSTR + nn] = self.z;
            fs[(d + 3) * FSTR + nn] = self.w;
            fs[(D + d + 0) * FSTR + nn] = m.x;
            fs[(D + d + 1) * FSTR + nn] = m.y;
            fs[(D + d + 2) * FSTR + nn] = m.z;
            fs[(D + d + 3) * FSTR + nn] = m.w;
        }
        __syncthreads();

        ull acc[4][4];
        #pragma unroll
        for (int i = 0; i < 4; i++)
            #pragma unroll
            for (int u = 0; u < 4; u++) acc[i][u] = bias2[u];

        const float* fb = fs + ng * 4;
        const float* wb = Ws + jg * 8;
        #pragma unroll 4
        for (int k = 0; k < 256; k++) {
            const float f0 = fb[k * FSTR + 0];
            const float f1 = fb[k * FSTR + 1];
            const float f2 = fb[k * FSTR + 2];
            const float f3 = fb[k * FSTR + 3];
            const ulonglong2 wa = *((const ulonglong2*)(wb + k * 128));
            const ulonglong2 wc = *((const ulonglong2*)(wb + k * 128 + 4));
            const ull w[4] = {wa.x, wa.y, wc.x, wc.y};
            const ull F0 = dup2(f0), F1 = dup2(f1), F2 = dup2(f2), F3 = dup2(f3);
            #pragma unroll
            for (int u = 0; u < 4; u++) {
                acc[0][u] = fma2(F0, w[u], acc[0][u]);
                acc[1][u] = fma2(F1, w[u], acc[1][u]);
                acc[2][u] = fma2(F2, w[u], acc[2][u]);
                acc[3][u] = fma2(F3, w[u], acc[3][u]);
            }
        }
        __syncthreads();

        #pragma unroll
        for (int i = 0; i < 4; i++) {
            const float2 p0 = unpk(acc[i][0]);
            const float2 p1 = unpk(acc[i][1]);
            const float2 p2 = unpk(acc[i][2]);
            const float2 p3 = unpk(acc[i][3]);
            h2s[(jg * 8 + 0) * FSTR + ng * 4 + i] = p0.x;
            h2s[(jg * 8 + 1) * FSTR + ng * 4 + i] = p0.y;
            h2s[(jg * 8 + 2) * FSTR + ng * 4 + i] = p1.x;
            h2s[(jg * 8 + 3) * FSTR + ng * 4 + i] = p1.y;
            h2s[(jg * 8 + 4) * FSTR + ng * 4 + i] = p2.x;
            h2s[(jg * 8 + 5) * FSTR + ng * 4 + i] = p2.y;
            h2s[(jg * 8 + 6) * FSTR + ng * 4 + i] = p3.x;
            h2s[(jg * 8 + 7) * FSTR + ng * 4 + i] = p3.y;
        }
        {
            const float4* src = (const float4*)Wout;
            float4* dst = (float4*)Wo;
            for (int i = tid; i < 128 * 64 / 4; i += NT) dst[i] = src[i];
        }
        __syncthreads();

        ull ao[4][2];
        #pragma unroll
        for (int i = 0; i < 4; i++) { ao[i][0] = biaso[0]; ao[i][1] = biaso[1]; }

        const float* hb = h2s + ng * 4;
        #pragma unroll 4
        for (int j = 0; j < 128; j++) {
            const float h0  = hb[j * FSTR + 0];
            const float h1v = hb[j * FSTR + 1];
            const float h2v = hb[j * FSTR + 2];
            const float h3  = hb[j * FSTR + 3];
            const ulonglong2 wv = *((const ulonglong2*)(Wo + j * 64 + og * 4));
            const ull H0 = dup2(h0), H1 = dup2(h1v), H2 = dup2(h2v), H3 = dup2(h3);
            ao[0][0] = fma2(H0, wv.x, ao[0][0]); ao[0][1] = fma2(H0, wv.y, ao[0][1]);
            ao[1][0] = fma2(H1, wv.x, ao[1][0]); ao[1][1] = fma2(H1, wv.y, ao[1][1]);
            ao[2][0] = fma2(H2, wv.x, ao[2][0]); ao[2][1] = fma2(H2, wv.y, ao[2][1]);
            ao[3][0] = fma2(H3, wv.x, ao[3][0]); ao[3][1] = fma2(H3, wv.y, ao[3][1]);
        }
        #pragma unroll
        for (int i = 0; i < 4; i++) {
            const float2 q0 = unpk(ao[i][0]);
            const float2 q1 = unpk(ao[i][1]);
            float4 ov = make_float4(q0.x, q0.y, q1.x, q1.y);
            *((float4*)(out + (size_t)(pos0 + ng * 4 + i) * 64 + og * 4)) = ov;
        }
        __syncthreads();
    }
}

// ---------------------------------------------------------------------------
extern "C" void kernel_launch(void* const* d_in, const int* in_sizes, int n_in,
                              void* d_out, int out_size)
{
    const float* x    = (const float*)d_in[0];
    const int*   nidx = (const int*)  d_in[1];
    const int*   batch= (const int*)  d_in[2];
    const float* W1   = (const float*)d_in[3];
    const float* b1   = (const float*)d_in[4];
    const float* W2   = (const float*)d_in[5];
    const float* b2   = (const float*)d_in[6];
    const float* Wout = (const float*)d_in[7];
    const float* bout = (const float*)d_in[8];
    float* out = (float*)d_out;

    const size_t smem1 = (256 * 128 + 2 * FS_FLOATS) * sizeof(float);   // 198656 B
    const size_t smem2 = (256 * 128 + 256 * FSTR) * sizeof(float)
                       + TILE2 * S * sizeof(int);

    cudaFuncSetAttribute((const void*)sage_layer1,
                         cudaFuncAttributeMaxDynamicSharedMemorySize, (int)smem1);
    cudaFuncSetAttribute((const void*)sage_layer2,
                         cudaFuncAttributeMaxDynamicSharedMemorySize, (int)smem2);

    sage_layer1<<<152, NT, smem1>>>(x, nidx, W1, b1);
    sage_layer2<<<128, NT, smem2>>>(nidx, batch, W2, b2, Wout, bout, out);
}

// round 6
// speedup vs baseline: 4.8357x; 1.2297x over previous
#include <cuda_runtime.h>
#include <cuda_bf16.h>
#include <cstdint>

#define NNODES 100000
#define D      128
#define S      16
#define NBATCH 8192
#define NT     256

typedef unsigned long long ull;

// ---- layer-1 config (warp-specialized, bf16-split mma.sync) ----
#define TILE1  32                    // nodes/tile (100000/32 = 3125 exact)
#define NTILES1 (NNODES / TILE1)
#define KSTR   264                   // bf16 row stride (256 + 8 pad)
// smem byte offsets
#define L1_BHI   0                   // Whi [128n][KSTR k] bf16  (67584)
#define L1_BLO   67584               // Wlo                      (67584)
#define L1_A0    135168              // 2 x (Ahi[32][KSTR] + Alo[32][KSTR])
#define L1_ABUF  33792               // bytes per A buffer (hi+lo)
#define L1_AHALF 16896               // bytes of Ahi within buffer
#define L1_BIAS  202752              // float[128]
#define SMEM1_SZ 203264

// ---- layer-2 (proven) config ----
#define TILE2  64
#define FSTR   65

__device__ float g_h1[(size_t)NNODES * D];

// ---------------- helpers ----------------
__device__ __forceinline__ ull fma2(ull a, ull b, ull c) {
    ull d;
    asm("fma.rn.f32x2 %0, %1, %2, %3;" : "=l"(d) : "l"(a), "l"(b), "l"(c));
    return d;
}
__device__ __forceinline__ ull pk2(float lo, float hi) {
    ull r; asm("mov.b64 %0, {%1, %2};" : "=l"(r) : "f"(lo), "f"(hi)); return r;
}
__device__ __forceinline__ ull dup2(float f) { return pk2(f, f); }
__device__ __forceinline__ float2 unpk(ull v) {
    float lo, hi; asm("mov.b64 {%0, %1}, %2;" : "=f"(lo), "=f"(hi) : "l"(v));
    return make_float2(lo, hi);
}
// pack 2 fp32 -> bf16x2 (element0 = lo arg in low 16 bits)
__device__ __forceinline__ uint32_t pbf2(float lo, float hi) {
    uint32_t r;
    asm("cvt.rn.bf16x2.f32 %0, %1, %2;" : "=r"(r) : "f"(hi), "f"(lo));
    return r;
}
__device__ __forceinline__ float bfr(float f) {
    return __bfloat162float(__float2bfloat16_rn(f));
}
__device__ __forceinline__ uint32_t lds32(uint32_t a) {
    uint32_t v; asm volatile("ld.shared.b32 %0, [%1];" : "=r"(v) : "r"(a)); return v;
}
__device__ __forceinline__ uint32_t smem_u32(const void* p) {
    uint32_t a;
    asm("{ .reg .u64 t; cvta.to.shared.u64 t, %1; cvt.u32.u64 %0, t; }"
        : "=r"(a) : "l"(p));
    return a;
}
__device__ __forceinline__ void mma_bf16(float c[4], uint32_t a0, uint32_t a1,
                                         uint32_t a2, uint32_t a3,
                                         uint32_t b0, uint32_t b1) {
    asm volatile(
        "mma.sync.aligned.m16n8k16.row.col.f32.bf16.bf16.f32 "
        "{%0,%1,%2,%3}, {%4,%5,%6,%7}, {%8,%9}, {%0,%1,%2,%3};"
        : "+f"(c[0]), "+f"(c[1]), "+f"(c[2]), "+f"(c[3])
        : "r"(a0), "r"(a1), "r"(a2), "r"(a3), "r"(b0), "r"(b1));
}

#define BAR_SYNC(id)   asm volatile("bar.sync %0, 256;"   :: "r"(id) : "memory")
#define BAR_ARRIVE(id) asm volatile("bar.arrive %0, 256;" :: "r"(id) : "memory")

// ---------------------------------------------------------------------------
// Layer 1: producer(gather,fp32 max,bf16 split) / consumer(mma.sync bf16x3)
// ---------------------------------------------------------------------------
extern "C" __global__ void __launch_bounds__(NT, 1)
sage_layer1(const float* __restrict__ x, const int* __restrict__ nidx,
            const float* __restrict__ W1, const float* __restrict__ b1)
{
    extern __shared__ char smem[];
    const uint32_t sb = smem_u32(smem);
    float* biass = (float*)(smem + L1_BIAS);

    const int tid = threadIdx.x;
    if (tid < 128) biass[tid] = b1[tid];

    // ---- stage W1 split+transposed: B[n][k] = W1[k][n] (hi/lo bf16) ----
    for (int i = tid; i < 256 * 128; i += NT) {
        const int k = i >> 7;            // coalesced read over n
        const int n = i & 127;
        const float w = W1[(size_t)k * 128 + n];
        const float h = bfr(w);
        *(__nv_bfloat16*)(smem + L1_BHI + (n * KSTR + k) * 2) = __float2bfloat16_rn(w);
        *(__nv_bfloat16*)(smem + L1_BLO + (n * KSTR + k) * 2) = __float2bfloat16_rn(w - h);
    }
    __syncthreads();

    if (tid < 128) {
        // ================= PRODUCER (warps 0-3) =================
        const int ptid = tid;
        for (int i = 0, tile = blockIdx.x; tile < NTILES1; tile += gridDim.x, i++) {
            const int b = i & 1;
            if (i >= 2) BAR_SYNC(3 + b);
            char* Ahi = smem + L1_A0 + b * L1_ABUF;
            char* Alo = Ahi + L1_AHALF;
            const int node0 = tile * TILE1;

            #pragma unroll 2
            for (int it = 0; it < 8; it++) {
                const int lin = ptid + it * 128;     // 0..1023
                const int nn  = lin >> 5;            // node 0..31 (warp-uniform)
                const int d4  = lin & 31;
                const int node = node0 + nn;

                const int4* np = (const int4*)(nidx + (size_t)node * S);
                const int4 na = np[0], nb4 = np[1], nc = np[2], nd = np[3];
                const int nb[16] = {na.x, na.y, na.z, na.w,
                                    nb4.x, nb4.y, nb4.z, nb4.w,
                                    nc.x, nc.y, nc.z, nc.w,
                                    nd.x, nd.y, nd.z, nd.w};

                const float4 self = *((const float4*)(x + (size_t)node * D) + d4);
                float4 m = *((const float4*)(x + (size_t)nb[0] * D) + d4);
                #pragma unroll
                for (int s = 1; s < S; s++) {
                    float4 v = *((const float4*)(x + (size_t)nb[s] * D) + d4);
                    m.x = fmaxf(m.x, v.x); m.y = fmaxf(m.y, v.y);
                    m.z = fmaxf(m.z, v.z); m.w = fmaxf(m.w, v.w);
                }
                const int ks = d4 * 4;        // self -> k = ks..ks+3
                const int ka = D + ks;        // agg  -> k = 128+ks..
                uint2 v;
                // self hi/lo
                v.x = pbf2(self.x, self.y); v.y = pbf2(self.z, self.w);
                *(uint2*)(Ahi + (nn * KSTR + ks) * 2) = v;
                v.x = pbf2(self.x - bfr(self.x), self.y - bfr(self.y));
                v.y = pbf2(self.z - bfr(self.z), self.w - bfr(self.w));
                *(uint2*)(Alo + (nn * KSTR + ks) * 2) = v;
                // agg hi/lo
                v.x = pbf2(m.x, m.y); v.y = pbf2(m.z, m.w);
                *(uint2*)(Ahi + (nn * KSTR + ka) * 2) = v;
                v.x = pbf2(m.x - bfr(m.x), m.y - bfr(m.y));
                v.y = pbf2(m.z - bfr(m.z), m.w - bfr(m.w));
                *(uint2*)(Alo + (nn * KSTR + ka) * 2) = v;
            }
            BAR_ARRIVE(1 + b);
        }
    } else {
        // ================= CONSUMER (warps 4-7): mma.sync =================
        const int w   = (tid - 128) >> 5;   // 0..3 -> n block w*32
        const int l   = tid & 31;
        const int qr  = l >> 2;             // l/4
        const int qc  = l & 3;              // l%4
        const int nbase = w * 32;

        for (int i = 0, tile = blockIdx.x; tile < NTILES1; tile += gridDim.x, i++) {
            const int b = i & 1;
            BAR_SYNC(1 + b);
            const uint32_t aHi = sb + L1_A0 + b * L1_ABUF;
            const uint32_t aLo = aHi + L1_AHALF;
            const int node0 = tile * TILE1;

            float acc[2][4][4];   // [m-tile][n-tile][frag]
            #pragma unroll
            for (int t = 0; t < 2; t++)
                #pragma unroll
                for (int j = 0; j < 4; j++)
                    #pragma unroll
                    for (int u = 0; u < 4; u++) acc[t][j][u] = 0.f;

            #pragma unroll 2
            for (int ks = 0; ks < 16; ks++) {
                const int k0 = ks * 16;
                // A fragments (2 m-tiles, hi+lo)
                uint32_t ah[2][4], al[2][4];
                #pragma unroll
                for (int t = 0; t < 2; t++) {
                    const uint32_t r0 = (uint32_t)(t * 16 + qr) * (KSTR * 2);
                    const uint32_t r1 = r0 + 8 * (KSTR * 2);
                    const uint32_t cA = (uint32_t)(k0 + 2 * qc) * 2;
                    ah[t][0] = lds32(aHi + r0 + cA);
                    ah[t][1] = lds32(aHi + r1 + cA);
                    ah[t][2] = lds32(aHi + r0 + cA + 16);
                    ah[t][3] = lds32(aHi + r1 + cA + 16);
                    al[t][0] = lds32(aLo + r0 + cA);
                    al[t][1] = lds32(aLo + r1 + cA);
                    al[t][2] = lds32(aLo + r0 + cA + 16);
                    al[t][3] = lds32(aLo + r1 + cA + 16);
                }
                // B fragments (4 n-tiles, hi+lo)
                uint32_t bh[4][2], bl[4][2];
                #pragma unroll
                for (int j = 0; j < 4; j++) {
                    const uint32_t nrow = (uint32_t)(nbase + j * 8 + qr) * (KSTR * 2);
                    const uint32_t cB = (uint32_t)(k0 + 2 * qc) * 2;
                    bh[j][0] = lds32(sb + L1_BHI + nrow + cB);
                    bh[j][1] = lds32(sb + L1_BHI + nrow + cB + 16);
                    bl[j][0] = lds32(sb + L1_BLO + nrow + cB);
                    bl[j][1] = lds32(sb + L1_BLO + nrow + cB + 16);
                }
                #pragma unroll
                for (int t = 0; t < 2; t++)
                    #pragma unroll
                    for (int j = 0; j < 4; j++) {
                        mma_bf16(acc[t][j], ah[t][0], ah[t][1], ah[t][2], ah[t][3],
                                 bh[j][0], bh[j][1]);
                        mma_bf16(acc[t][j], ah[t][0], ah[t][1], ah[t][2], ah[t][3],
                                 bl[j][0], bl[j][1]);
                        mma_bf16(acc[t][j], al[t][0], al[t][1], al[t][2], al[t][3],
                                 bh[j][0], bh[j][1]);
                    }
            }
            BAR_ARRIVE(3 + b);   // buffer free (results live in regs)

            // epilogue: bias + relu -> g_h1
            #pragma unroll
            for (int t = 0; t < 2; t++) {
                const int r0 = node0 + t * 16 + qr;
                #pragma unroll
                for (int j = 0; j < 4; j++) {
                    const int n = nbase + j * 8 + 2 * qc;
                    const float bi0 = biass[n], bi1 = biass[n + 1];
                    float2 v0, v1;
                    v0.x = fmaxf(acc[t][j][0] + bi0, 0.f);
                    v0.y = fmaxf(acc[t][j][1] + bi1, 0.f);
                    v1.x = fmaxf(acc[t][j][2] + bi0, 0.f);
                    v1.y = fmaxf(acc[t][j][3] + bi1, 0.f);
                    *(float2*)(g_h1 + (size_t)r0 * D + n) = v0;
                    *(float2*)(g_h1 + (size_t)(r0 + 8) * D + n) = v1;
                }
            }
        }
    }
}

// ---------------------------------------------------------------------------
// Layer 2 + proj_out (batch nodes only), FFMA2 fp32 (round-4/5 proven).
// ---------------------------------------------------------------------------
extern "C" __global__ void __launch_bounds__(NT, 1)
sage_layer2(const int* __restrict__ nidx, const int* __restrict__ batch,
            const float* __restrict__ W2, const float* __restrict__ b2,
            const float* __restrict__ Wout, const float* __restrict__ bout,
            float* __restrict__ out)
{
    extern __shared__ float smemf[];
    float* Ws  = smemf;
    float* fs  = Ws + 256 * 128;
    int*   nbs = (int*)(fs + 256 * FSTR);
    float* h2s = fs;
    float* Wo  = fs + 128 * FSTR;

    const int tid = threadIdx.x;

    {
        const float4* src = (const float4*)W2;
        float4* dst = (float4*)Ws;
        for (int i = tid; i < 256 * 128 / 4; i += NT) dst[i] = src[i];
    }

    const int ng = tid & 15;
    const int jg = tid >> 4;
    ull bias2[4];
    {
        float4 b0 = *((const float4*)(b2 + jg * 8));
        float4 b4 = *((const float4*)(b2 + jg * 8 + 4));
        bias2[0] = pk2(b0.x, b0.y); bias2[1] = pk2(b0.z, b0.w);
        bias2[2] = pk2(b4.x, b4.y); bias2[3] = pk2(b4.z, b4.w);
    }
    const int og = tid >> 4;
    ull biaso[2];
    {
        float4 bo = *((const float4*)(bout + og * 4));
        biaso[0] = pk2(bo.x, bo.y); biaso[1] = pk2(bo.z, bo.w);
    }
    __syncthreads();

    const int numTiles = NBATCH / TILE2;
    for (int tile = blockIdx.x; tile < numTiles; tile += gridDim.x) {
        const int pos0 = tile * TILE2;

        for (int i = tid; i < TILE2 * S; i += NT) {
            const int bnode = __ldg(batch + pos0 + (i >> 4));
            nbs[i] = nidx[(size_t)bnode * S + (i & 15)];
        }
        __syncthreads();

        for (int it = 0; it < 8; it++) {
            const int lin = tid + it * NT;
            const int nn  = lin >> 5;
            const int d4  = lin & 31;
            const int bnode = __ldg(batch + pos0 + nn);
            const float4 self = *((const float4*)(g_h1 + (size_t)bnode * D) + d4);
            const int* nb = &nbs[nn * S];
            float4 m = *((const float4*)(g_h1 + (size_t)nb[0] * D) + d4);
            #pragma unroll
            for (int s = 1; s < S; s++) {
                float4 v = *((const float4*)(g_h1 + (size_t)nb[s] * D) + d4);
                m.x = fmaxf(m.x, v.x); m.y = fmaxf(m.y, v.y);
                m.z = fmaxf(m.z, v.z); m.w = fmaxf(m.w, v.w);
            }
            const int d = d4 * 4;
            fs[(d + 0) * FSTR + nn] = self.x;
            fs[(d + 1) * FSTR + nn] = self.y;
            fs[(d + 2) * FSTR + nn] = self.z;
            fs[(d + 3) * FSTR + nn] = self.w;
            fs[(D + d + 0) * FSTR + nn] = m.x;
            fs[(D + d + 1) * FSTR + nn] = m.y;
            fs[(D + d + 2) * FSTR + nn] = m.z;
            fs[(D + d + 3) * FSTR + nn] = m.w;
        }
        __syncthreads();

        ull acc[4][4];
        #pragma unroll
        for (int i = 0; i < 4; i++)
            #pragma unroll
            for (int u = 0; u < 4; u++) acc[i][u] = bias2[u];

        const float* fb = fs + ng * 4;
        const float* wb = Ws + jg * 8;
        #pragma unroll 4
        for (int k = 0; k < 256; k++) {
            const float f0 = fb[k * FSTR + 0];
            const float f1 = fb[k * FSTR + 1];
            const float f2 = fb[k * FSTR + 2];
            const float f3 = fb[k * FSTR + 3];
            const ulonglong2 wa = *((const ulonglong2*)(wb + k * 128));
            const ulonglong2 wc = *((const ulonglong2*)(wb + k * 128 + 4));
            const ull wv[4] = {wa.x, wa.y, wc.x, wc.y};
            const ull F0 = dup2(f0), F1 = dup2(f1), F2 = dup2(f2), F3 = dup2(f3);
            #pragma unroll
            for (int u = 0; u < 4; u++) {
                acc[0][u] = fma2(F0, wv[u], acc[0][u]);
                acc[1][u] = fma2(F1, wv[u], acc[1][u]);
                acc[2][u] = fma2(F2, wv[u], acc[2][u]);
                acc[3][u] = fma2(F3, wv[u], acc[3][u]);
            }
        }
        __syncthreads();

        #pragma unroll
        for (int i = 0; i < 4; i++) {
            const float2 p0 = unpk(acc[i][0]);
            const float2 p1 = unpk(acc[i][1]);
            const float2 p2 = unpk(acc[i][2]);
            const float2 p3 = unpk(acc[i][3]);
            h2s[(jg * 8 + 0) * FSTR + ng * 4 + i] = p0.x;
            h2s[(jg * 8 + 1) * FSTR + ng * 4 + i] = p0.y;
            h2s[(jg * 8 + 2) * FSTR + ng * 4 + i] = p1.x;
            h2s[(jg * 8 + 3) * FSTR + ng * 4 + i] = p1.y;
            h2s[(jg * 8 + 4) * FSTR + ng * 4 + i] = p2.x;
            h2s[(jg * 8 + 5) * FSTR + ng * 4 + i] = p2.y;
            h2s[(jg * 8 + 6) * FSTR + ng * 4 + i] = p3.x;
            h2s[(jg * 8 + 7) * FSTR + ng * 4 + i] = p3.y;
        }
        {
            const float4* src = (const float4*)Wout;
            float4* dst = (float4*)Wo;
            for (int i = tid; i < 128 * 64 / 4; i += NT) dst[i] = src[i];
        }
        __syncthreads();

        ull ao[4][2];
        #pragma unroll
        for (int i = 0; i < 4; i++) { ao[i][0] = biaso[0]; ao[i][1] = biaso[1]; }

        const float* hb = h2s + ng * 4;
        #pragma unroll 4
        for (int j = 0; j < 128; j++) {
            const float h0  = hb[j * FSTR + 0];
            const float h1v = hb[j * FSTR + 1];
            const float h2v = hb[j * FSTR + 2];
            const float h3  = hb[j * FSTR + 3];
            const ulonglong2 wv = *((const ulonglong2*)(Wo + j * 64 + og * 4));
            const ull H0 = dup2(h0), H1 = dup2(h1v), H2 = dup2(h2v), H3 = dup2(h3);
            ao[0][0] = fma2(H0, wv.x, ao[0][0]); ao[0][1] = fma2(H0, wv.y, ao[0][1]);
            ao[1][0] = fma2(H1, wv.x, ao[1][0]); ao[1][1] = fma2(H1, wv.y, ao[1][1]);
            ao[2][0] = fma2(H2, wv.x, ao[2][0]); ao[2][1] = fma2(H2, wv.y, ao[2][1]);
            ao[3][0] = fma2(H3, wv.x, ao[3][0]); ao[3][1] = fma2(H3, wv.y, ao[3][1]);
        }
        #pragma unroll
        for (int i = 0; i < 4; i++) {
            const float2 q0 = unpk(ao[i][0]);
            const float2 q1 = unpk(ao[i][1]);
            float4 ov = make_float4(q0.x, q0.y, q1.x, q1.y);
            *((float4*)(out + (size_t)(pos0 + ng * 4 + i) * 64 + og * 4)) = ov;
        }
        __syncthreads();
    }
}

// ---------------------------------------------------------------------------
extern "C" void kernel_launch(void* const* d_in, const int* in_sizes, int n_in,
                              void* d_out, int out_size)
{
    const float* x    = (const float*)d_in[0];
    const int*   nidx = (const int*)  d_in[1];
    const int*   batch= (const int*)  d_in[2];
    const float* W1   = (const float*)d_in[3];
    const float* b1   = (const float*)d_in[4];
    const float* W2   = (const float*)d_in[5];
    const float* b2   = (const float*)d_in[6];
    const float* Wout = (const float*)d_in[7];
    const float* bout = (const float*)d_in[8];
    float* out = (float*)d_out;

    const size_t smem2 = (256 * 128 + 256 * FSTR) * sizeof(float)
                       + TILE2 * S * sizeof(int);

    cudaFuncSetAttribute((const void*)sage_layer1,
                         cudaFuncAttributeMaxDynamicSharedMemorySize, SMEM1_SZ);
    cudaFuncSetAttribute((const void*)sage_layer2,
                         cudaFuncAttributeMaxDynamicSharedMemorySize, (int)smem2);

    sage_layer1<<<152, NT, SMEM1_SZ>>>(x, nidx, W1, b1);
    sage_layer2<<<128, NT, smem2>>>(nidx, batch, W2, b2, Wout, bout, out);
}

// round 7
// speedup vs baseline: 5.9399x; 1.2283x over previous
#include <cuda_runtime.h>
#include <cuda_bf16.h>
#include <cstdint>

#define NNODES 100000
#define D      128
#define S      16
#define NBATCH 8192
#define NT1    384
#define NT2    384

typedef unsigned long long ull;

#define TILE1  32
#define NTILES1 (NNODES / TILE1)     // 3125
#define NTILES2 (NBATCH / TILE1)     // 256
#define KSTR   264                   // bf16 row stride (256 + 8 pad)

// ---- layer-1 smem offsets ----
#define L1_BHI   0                   // Whi [128][KSTR] bf16  (67584)
#define L1_BLO   67584
#define L1_A0    135168              // 2 x (Ahi[32][KSTR] + Alo[32][KSTR])
#define L1_ABUF  33792
#define L1_AHALF 16896
#define L1_BIAS  202752              // float[128]
#define SMEM1_SZ 203264

// ---- layer-2 smem offsets ----
#define L2_BHI   0                   // W2p hi [64][KSTR] bf16 (33792)
#define L2_BLO   33792
#define L2_A0    67584               // 2 x (Ahi+Alo)
#define L2_BIAS  135168              // float[64]
#define SMEM2_SZ 135424

__device__ float g_h1[(size_t)NNODES * D];
__device__ float g_W2p[256 * 64];    // W2 @ Wout
__device__ float g_b2p[64];          // b2 @ Wout + bout

// ---------------- helpers ----------------
__device__ __forceinline__ uint32_t pbf2(float lo, float hi) {
    uint32_t r;
    asm("cvt.rn.bf16x2.f32 %0, %1, %2;" : "=r"(r) : "f"(hi), "f"(lo));
    return r;
}
__device__ __forceinline__ float bfr(float f) {
    return __bfloat162float(__float2bfloat16_rn(f));
}
__device__ __forceinline__ uint32_t lds32(uint32_t a) {
    uint32_t v; asm volatile("ld.shared.b32 %0, [%1];" : "=r"(v) : "r"(a)); return v;
}
__device__ __forceinline__ uint32_t smem_u32(const void* p) {
    uint32_t a;
    asm("{ .reg .u64 t; cvta.to.shared.u64 t, %1; cvt.u32.u64 %0, t; }"
        : "=r"(a) : "l"(p));
    return a;
}
__device__ __forceinline__ void mma_bf16(float c[4], uint32_t a0, uint32_t a1,
                                         uint32_t a2, uint32_t a3,
                                         uint32_t b0, uint32_t b1) {
    asm volatile(
        "mma.sync.aligned.m16n8k16.row.col.f32.bf16.bf16.f32 "
        "{%0,%1,%2,%3}, {%4,%5,%6,%7}, {%8,%9}, {%0,%1,%2,%3};"
        : "+f"(c[0]), "+f"(c[1]), "+f"(c[2]), "+f"(c[3])
        : "r"(a0), "r"(a1), "r"(a2), "r"(a3), "r"(b0), "r"(b1));
}

#define BAR_SYNC(id, n)   asm volatile("bar.sync %0, %1;"   :: "r"(id), "r"(n) : "memory")
#define BAR_ARRIVE(id, n) asm volatile("bar.arrive %0, %1;" :: "r"(id), "r"(n) : "memory")

// producer gather+split body (shared by both layers)
__device__ __forceinline__ void gather_split(
    const float* __restrict__ src, const int* nb, int node, int nn, int d4,
    char* Ahi, char* Alo)
{
    const float4 self = *((const float4*)(src + (size_t)node * D) + d4);
    float4 m = *((const float4*)(src + (size_t)nb[0] * D) + d4);
    #pragma unroll
    for (int s = 1; s < S; s++) {
        float4 v = *((const float4*)(src + (size_t)nb[s] * D) + d4);
        m.x = fmaxf(m.x, v.x); m.y = fmaxf(m.y, v.y);
        m.z = fmaxf(m.z, v.z); m.w = fmaxf(m.w, v.w);
    }
    const int ks = d4 * 4;
    const int ka = D + ks;
    uint2 v;
    v.x = pbf2(self.x, self.y); v.y = pbf2(self.z, self.w);
    *(uint2*)(Ahi + (nn * KSTR + ks) * 2) = v;
    v.x = pbf2(self.x - bfr(self.x), self.y - bfr(self.y));
    v.y = pbf2(self.z - bfr(self.z), self.w - bfr(self.w));
    *(uint2*)(Alo + (nn * KSTR + ks) * 2) = v;
    v.x = pbf2(m.x, m.y); v.y = pbf2(m.z, m.w);
    *(uint2*)(Ahi + (nn * KSTR + ka) * 2) = v;
    v.x = pbf2(m.x - bfr(m.x), m.y - bfr(m.y));
    v.y = pbf2(m.z - bfr(m.z), m.w - bfr(m.w));
    *(uint2*)(Alo + (nn * KSTR + ka) * 2) = v;
}

// ---------------------------------------------------------------------------
// prep: W2p = W2 @ Wout ; b2p = b2 @ Wout + bout
// ---------------------------------------------------------------------------
extern "C" __global__ void prep_w2p(const float* __restrict__ W2,
                                    const float* __restrict__ b2,
                                    const float* __restrict__ Wout,
                                    const float* __restrict__ bout)
{
    const int idx = blockIdx.x * blockDim.x + threadIdx.x;   // 0..16383
    const int k = idx >> 6, n = idx & 63;
    float s = 0.f;
    #pragma unroll 8
    for (int j = 0; j < 128; j++) s += W2[k * 128 + j] * Wout[j * 64 + n];
    g_W2p[k * 64 + n] = s;
    if (idx < 64) {
        float t = bout[idx];
        #pragma unroll 8
        for (int j = 0; j < 128; j++) t += b2[j] * Wout[j * 64 + idx];
        g_b2p[idx] = t;
    }
}

// ---------------------------------------------------------------------------
// Layer 1: 8 producer warps (gather) / 4 consumer warps (mma.sync bf16x3)
// ---------------------------------------------------------------------------
extern "C" __global__ void __launch_bounds__(NT1, 1)
sage_layer1(const float* __restrict__ x, const int* __restrict__ nidx,
            const float* __restrict__ W1, const float* __restrict__ b1)
{
    extern __shared__ char smem[];
    const uint32_t sb = smem_u32(smem);
    float* biass = (float*)(smem + L1_BIAS);

    const int tid = threadIdx.x;
    if (tid < 128) biass[tid] = b1[tid];

    // stage W1 split+transposed: B[n][k] = W1[k][n]
    for (int i = tid; i < 256 * 128; i += NT1) {
        const int k = i >> 7, n = i & 127;
        const float w = W1[(size_t)k * 128 + n];
        const float h = bfr(w);
        *(__nv_bfloat16*)(smem + L1_BHI + (n * KSTR + k) * 2) = __float2bfloat16_rn(w);
        *(__nv_bfloat16*)(smem + L1_BLO + (n * KSTR + k) * 2) = __float2bfloat16_rn(w - h);
    }
    __syncthreads();

    if (tid < 256) {
        // ============ PRODUCERS (warps 0-7) ============
        for (int i = 0, tile = blockIdx.x; tile < NTILES1; tile += gridDim.x, i++) {
            const int b = i & 1;
            if (i >= 2) BAR_SYNC(3 + b, NT1);
            char* Ahi = smem + L1_A0 + b * L1_ABUF;
            char* Alo = Ahi + L1_AHALF;
            const int node0 = tile * TILE1;

            #pragma unroll
            for (int it = 0; it < 4; it++) {
                const int lin = tid + it * 256;      // 0..1023
                const int nn  = lin >> 5;            // warp-uniform
                const int d4  = lin & 31;
                const int node = node0 + nn;
                const int4* np = (const int4*)(nidx + (size_t)node * S);
                const int4 na = np[0], nb4 = np[1], nc = np[2], nd = np[3];
                const int nb[16] = {na.x, na.y, na.z, na.w, nb4.x, nb4.y, nb4.z, nb4.w,
                                    nc.x, nc.y, nc.z, nc.w, nd.x, nd.y, nd.z, nd.w};
                gather_split(x, nb, node, nn, d4, Ahi, Alo);
            }
            BAR_ARRIVE(1 + b, NT1);
        }
    } else {
        // ============ CONSUMERS (warps 8-11) ============
        const int w  = (tid - 256) >> 5;
        const int l  = tid & 31;
        const int qr = l >> 2, qc = l & 3;
        const int nbase = w * 32;

        for (int i = 0, tile = blockIdx.x; tile < NTILES1; tile += gridDim.x, i++) {
            const int b = i & 1;
            BAR_SYNC(1 + b, NT1);
            const uint32_t aHi = sb + L1_A0 + b * L1_ABUF;
            const uint32_t aLo = aHi + L1_AHALF;
            const int node0 = tile * TILE1;

            float acc[2][4][4];
            #pragma unroll
            for (int t = 0; t < 2; t++)
                #pragma unroll
                for (int j = 0; j < 4; j++)
                    #pragma unroll
                    for (int u = 0; u < 4; u++) acc[t][j][u] = 0.f;

            #pragma unroll 2
            for (int ks = 0; ks < 16; ks++) {
                const int k0 = ks * 16;
                uint32_t ah[2][4], al[2][4];
                #pragma unroll
                for (int t = 0; t < 2; t++) {
                    const uint32_t r0 = (uint32_t)(t * 16 + qr) * (KSTR * 2);
                    const uint32_t r1 = r0 + 8 * (KSTR * 2);
                    const uint32_t cA = (uint32_t)(k0 + 2 * qc) * 2;
                    ah[t][0] = lds32(aHi + r0 + cA);  ah[t][1] = lds32(aHi + r1 + cA);
                    ah[t][2] = lds32(aHi + r0 + cA + 16); ah[t][3] = lds32(aHi + r1 + cA + 16);
                    al[t][0] = lds32(aLo + r0 + cA);  al[t][1] = lds32(aLo + r1 + cA);
                    al[t][2] = lds32(aLo + r0 + cA + 16); al[t][3] = lds32(aLo + r1 + cA + 16);
                }
                uint32_t bh[4][2], bl[4][2];
                #pragma unroll
                for (int j = 0; j < 4; j++) {
                    const uint32_t nrow = (uint32_t)(nbase + j * 8 + qr) * (KSTR * 2);
                    const uint32_t cB = (uint32_t)(k0 + 2 * qc) * 2;
                    bh[j][0] = lds32(sb + L1_BHI + nrow + cB);
                    bh[j][1] = lds32(sb + L1_BHI + nrow + cB + 16);
                    bl[j][0] = lds32(sb + L1_BLO + nrow + cB);
                    bl[j][1] = lds32(sb + L1_BLO + nrow + cB + 16);
                }
                #pragma unroll
                for (int t = 0; t < 2; t++)
                    #pragma unroll
                    for (int j = 0; j < 4; j++) {
                        mma_bf16(acc[t][j], ah[t][0], ah[t][1], ah[t][2], ah[t][3],
                                 bh[j][0], bh[j][1]);
                        mma_bf16(acc[t][j], ah[t][0], ah[t][1], ah[t][2], ah[t][3],
                                 bl[j][0], bl[j][1]);
                        mma_bf16(acc[t][j], al[t][0], al[t][1], al[t][2], al[t][3],
                                 bh[j][0], bh[j][1]);
                    }
            }
            BAR_ARRIVE(3 + b, NT1);

            #pragma unroll
            for (int t = 0; t < 2; t++) {
                const int r0 = node0 + t * 16 + qr;
                #pragma unroll
                for (int j = 0; j < 4; j++) {
                    const int n = nbase + j * 8 + 2 * qc;
                    const float bi0 = biass[n], bi1 = biass[n + 1];
                    float2 v0, v1;
                    v0.x = fmaxf(acc[t][j][0] + bi0, 0.f);
                    v0.y = fmaxf(acc[t][j][1] + bi1, 0.f);
                    v1.x = fmaxf(acc[t][j][2] + bi0, 0.f);
                    v1.y = fmaxf(acc[t][j][3] + bi1, 0.f);
                    *(float2*)(g_h1 + (size_t)r0 * D + n) = v0;
                    *(float2*)(g_h1 + (size_t)(r0 + 8) * D + n) = v1;
                }
            }
        }
    }
}

// ---------------------------------------------------------------------------
// Layer 2 fused: out = concat(h1[b], max h1[neigh[b]]) @ W2p + b2p
// Same warp-specialized structure; N=64.
// ---------------------------------------------------------------------------
extern "C" __global__ void __launch_bounds__(NT2, 1)
sage_layer2(const int* __restrict__ nidx, const int* __restrict__ batch,
            float* __restrict__ out)
{
    extern __shared__ char smem[];
    const uint32_t sb = smem_u32(smem);
    float* biass = (float*)(smem + L2_BIAS);

    const int tid = threadIdx.x;
    if (tid < 64) biass[tid] = g_b2p[tid];

    // stage W2p split+transposed: B[n][k] = W2p[k][n], n<64
    for (int i = tid; i < 256 * 64; i += NT2) {
        const int k = i >> 6, n = i & 63;
        const float w = g_W2p[k * 64 + n];
        const float h = bfr(w);
        *(__nv_bfloat16*)(smem + L2_BHI + (n * KSTR + k) * 2) = __float2bfloat16_rn(w);
        *(__nv_bfloat16*)(smem + L2_BLO + (n * KSTR + k) * 2) = __float2bfloat16_rn(w - h);
    }
    __syncthreads();

    if (tid < 256) {
        // ============ PRODUCERS ============
        for (int i = 0, tile = blockIdx.x; tile < NTILES2; tile += gridDim.x, i++) {
            const int b = i & 1;
            if (i >= 2) BAR_SYNC(3 + b, NT2);
            char* Ahi = smem + L2_A0 + b * L1_ABUF;
            char* Alo = Ahi + L1_AHALF;
            const int pos0 = tile * TILE1;

            #pragma unroll
            for (int it = 0; it < 4; it++) {
                const int lin = tid + it * 256;
                const int nn  = lin >> 5;
                const int d4  = lin & 31;
                const int bnode = __ldg(batch + pos0 + nn);
                const int4* np = (const int4*)(nidx + (size_t)bnode * S);
                const int4 na = np[0], nb4 = np[1], nc = np[2], nd = np[3];
                const int nb[16] = {na.x, na.y, na.z, na.w, nb4.x, nb4.y, nb4.z, nb4.w,
                                    nc.x, nc.y, nc.z, nc.w, nd.x, nd.y, nd.z, nd.w};
                gather_split(g_h1, nb, bnode, nn, d4, Ahi, Alo);
            }
            BAR_ARRIVE(1 + b, NT2);
        }
    } else {
        // ============ CONSUMERS (4 warps, n-block 16 each) ============
        const int w  = (tid - 256) >> 5;
        const int l  = tid & 31;
        const int qr = l >> 2, qc = l & 3;
        const int nbase = w * 16;

        for (int i = 0, tile = blockIdx.x; tile < NTILES2; tile += gridDim.x, i++) {
            const int b = i & 1;
            BAR_SYNC(1 + b, NT2);
            const uint32_t aHi = sb + L2_A0 + b * L1_ABUF;
            const uint32_t aLo = aHi + L1_AHALF;
            const int pos0 = tile * TILE1;

            float acc[2][2][4];
            #pragma unroll
            for (int t = 0; t < 2; t++)
                #pragma unroll
                for (int j = 0; j < 2; j++)
                    #pragma unroll
                    for (int u = 0; u < 4; u++) acc[t][j][u] = 0.f;

            #pragma unroll 2
            for (int ks = 0; ks < 16; ks++) {
                const int k0 = ks * 16;
                uint32_t ah[2][4], al[2][4];
                #pragma unroll
                for (int t = 0; t < 2; t++) {
                    const uint32_t r0 = (uint32_t)(t * 16 + qr) * (KSTR * 2);
                    const uint32_t r1 = r0 + 8 * (KSTR * 2);
                    const uint32_t cA = (uint32_t)(k0 + 2 * qc) * 2;
                    ah[t][0] = lds32(aHi + r0 + cA);  ah[t][1] = lds32(aHi + r1 + cA);
                    ah[t][2] = lds32(aHi + r0 + cA + 16); ah[t][3] = lds32(aHi + r1 + cA + 16);
                    al[t][0] = lds32(aLo + r0 + cA);  al[t][1] = lds32(aLo + r1 + cA);
                    al[t][2] = lds32(aLo + r0 + cA + 16); al[t][3] = lds32(aLo + r1 + cA + 16);
                }
                uint32_t bh[2][2], bl[2][2];
                #pragma unroll
                for (int j = 0; j < 2; j++) {
                    const uint32_t nrow = (uint32_t)(nbase + j * 8 + qr) * (KSTR * 2);
                    const uint32_t cB = (uint32_t)(k0 + 2 * qc) * 2;
                    bh[j][0] = lds32(sb + L2_BHI + nrow + cB);
                    bh[j][1] = lds32(sb + L2_BHI + nrow + cB + 16);
                    bl[j][0] = lds32(sb + L2_BLO + nrow + cB);
                    bl[j][1] = lds32(sb + L2_BLO + nrow + cB + 16);
                }
                #pragma unroll
                for (int t = 0; t < 2; t++)
                    #pragma unroll
                    for (int j = 0; j < 2; j++) {
                        mma_bf16(acc[t][j], ah[t][0], ah[t][1], ah[t][2], ah[t][3],
                                 bh[j][0], bh[j][1]);
                        mma_bf16(acc[t][j], ah[t][0], ah[t][1], ah[t][2], ah[t][3],
                                 bl[j][0], bl[j][1]);
                        mma_bf16(acc[t][j], al[t][0], al[t][1], al[t][2], al[t][3],
                                 bh[j][0], bh[j][1]);
                    }
            }
            BAR_ARRIVE(3 + b, NT2);

            #pragma unroll
            for (int t = 0; t < 2; t++) {
                const int r0 = pos0 + t * 16 + qr;
                #pragma unroll
                for (int j = 0; j < 2; j++) {
                    const int n = nbase + j * 8 + 2 * qc;
                    const float bi0 = biass[n], bi1 = biass[n + 1];
                    float2 v0, v1;
                    v0.x = acc[t][j][0] + bi0;
                    v0.y = acc[t][j][1] + bi1;
                    v1.x = acc[t][j][2] + bi0;
                    v1.y = acc[t][j][3] + bi1;
                    *(float2*)(out + (size_t)r0 * 64 + n) = v0;
                    *(float2*)(out + (size_t)(r0 + 8) * 64 + n) = v1;
                }
            }
        }
    }
}

// ---------------------------------------------------------------------------
extern "C" void kernel_launch(void* const* d_in, const int* in_sizes, int n_in,
                              void* d_out, int out_size)
{
    const float* x    = (const float*)d_in[0];
    const int*   nidx = (const int*)  d_in[1];
    const int*   batch= (const int*)  d_in[2];
    const float* W1   = (const float*)d_in[3];
    const float* b1   = (const float*)d_in[4];
    const float* W2   = (const float*)d_in[5];
    const float* b2   = (const float*)d_in[6];
    const float* Wout = (const float*)d_in[7];
    const float* bout = (const float*)d_in[8];
    float* out = (float*)d_out;

    cudaFuncSetAttribute((const void*)sage_layer1,
                         cudaFuncAttributeMaxDynamicSharedMemorySize, SMEM1_SZ);
    cudaFuncSetAttribute((const void*)sage_layer2,
                         cudaFuncAttributeMaxDynamicSharedMemorySize, SMEM2_SZ);

    prep_w2p<<<32, 512>>>(W2, b2, Wout, bout);
    sage_layer1<<<152, NT1, SMEM1_SZ>>>(x, nidx, W1, b1);
    sage_layer2<<<152, NT2, SMEM2_SZ>>>(nidx, batch, out);
}

// round 8
// speedup vs baseline: 6.1675x; 1.0383x over previous
#include <cuda_runtime.h>
#include <cuda_bf16.h>
#include <cstdint>

#define NNODES 100000
#define D      128
#define S      16
#define NBATCH 8192
#define NT1    384

#define TILE1  32
#define NTILES1 (NNODES / TILE1)     // 3125
#define KSTR   264                   // bf16 row stride (256 + 8 pad)

// ---- layer-1 smem offsets ----
#define L1_BHI   0                   // Whi [128][KSTR] bf16  (67584)
#define L1_BLO   67584
#define L1_A0    135168              // 2 x (Ahi[32][KSTR] + Alo[32][KSTR])
#define L1_ABUF  33792
#define L1_AHALF 16896
#define L1_BIAS  202752              // float[128]
#define SMEM1_SZ 203264

// ---- layer-2 smem offsets (single 64-node tile) ----
#define L2_BHI   0                   // W2p hi [64][KSTR] bf16 (33792)
#define L2_BLO   33792
#define L2_AHI   67584               // Ahi [64][KSTR] (33792)
#define L2_ALO   101376              // Alo            (33792)
#define L2_BIAS  135168              // float[64]
#define SMEM2_SZ 135424
#define NT2      256
#define TILE2    64

__device__ float g_h1[(size_t)NNODES * D];
__device__ float g_W2p[256 * 64];    // W2 @ Wout
__device__ float g_b2p[64];          // b2 @ Wout + bout

// ---------------- helpers ----------------
__device__ __forceinline__ uint32_t pbf2(float lo, float hi) {
    uint32_t r;
    asm("cvt.rn.bf16x2.f32 %0, %1, %2;" : "=r"(r) : "f"(hi), "f"(lo));
    return r;
}
__device__ __forceinline__ float bfr(float f) {
    return __bfloat162float(__float2bfloat16_rn(f));
}
__device__ __forceinline__ uint32_t lds32(uint32_t a) {
    uint32_t v; asm volatile("ld.shared.b32 %0, [%1];" : "=r"(v) : "r"(a)); return v;
}
__device__ __forceinline__ uint32_t smem_u32(const void* p) {
    uint32_t a;
    asm("{ .reg .u64 t; cvta.to.shared.u64 t, %1; cvt.u32.u64 %0, t; }"
        : "=r"(a) : "l"(p));
    return a;
}
__device__ __forceinline__ void mma_bf16(float c[4], uint32_t a0, uint32_t a1,
                                         uint32_t a2, uint32_t a3,
                                         uint32_t b0, uint32_t b1) {
    asm volatile(
        "mma.sync.aligned.m16n8k16.row.col.f32.bf16.bf16.f32 "
        "{%0,%1,%2,%3}, {%4,%5,%6,%7}, {%8,%9}, {%0,%1,%2,%3};"
        : "+f"(c[0]), "+f"(c[1]), "+f"(c[2]), "+f"(c[3])
        : "r"(a0), "r"(a1), "r"(a2), "r"(a3), "r"(b0), "r"(b1));
}

#define BAR_SYNC(id, n)   asm volatile("bar.sync %0, %1;"   :: "r"(id), "r"(n) : "memory")
#define BAR_ARRIVE(id, n) asm volatile("bar.arrive %0, %1;" :: "r"(id), "r"(n) : "memory")

// producer gather+split body
__device__ __forceinline__ void gather_split(
    const float* __restrict__ src, const int* nb, int node, int nn, int d4,
    char* Ahi, char* Alo)
{
    const float4 self = *((const float4*)(src + (size_t)node * D) + d4);
    float4 m = *((const float4*)(src + (size_t)nb[0] * D) + d4);
    #pragma unroll
    for (int s = 1; s < S; s++) {
        float4 v = *((const float4*)(src + (size_t)nb[s] * D) + d4);
        m.x = fmaxf(m.x, v.x); m.y = fmaxf(m.y, v.y);
        m.z = fmaxf(m.z, v.z); m.w = fmaxf(m.w, v.w);
    }
    const int ks = d4 * 4;
    const int ka = D + ks;
    uint2 v;
    v.x = pbf2(self.x, self.y); v.y = pbf2(self.z, self.w);
    *(uint2*)(Ahi + (nn * KSTR + ks) * 2) = v;
    v.x = pbf2(self.x - bfr(self.x), self.y - bfr(self.y));
    v.y = pbf2(self.z - bfr(self.z), self.w - bfr(self.w));
    *(uint2*)(Alo + (nn * KSTR + ks) * 2) = v;
    v.x = pbf2(m.x, m.y); v.y = pbf2(m.z, m.w);
    *(uint2*)(Ahi + (nn * KSTR + ka) * 2) = v;
    v.x = pbf2(m.x - bfr(m.x), m.y - bfr(m.y));
    v.y = pbf2(m.z - bfr(m.z), m.w - bfr(m.w));
    *(uint2*)(Alo + (nn * KSTR + ka) * 2) = v;
}

// ---------------------------------------------------------------------------
// prep: W2p = W2 @ Wout ; b2p = b2 @ Wout + bout.  Full-chip, 4-acc ILP.
// ---------------------------------------------------------------------------
extern "C" __global__ void __launch_bounds__(128, 1)
prep_w2p(const float* __restrict__ W2, const float* __restrict__ b2,
         const float* __restrict__ Wout, const float* __restrict__ bout)
{
    const int idx = blockIdx.x * 128 + threadIdx.x;   // 0..16383
    const int k = idx >> 6, n = idx & 63;
    float s0 = 0.f, s1 = 0.f, s2 = 0.f, s3 = 0.f;
    #pragma unroll 8
    for (int j = 0; j < 128; j += 4) {
        s0 += W2[k * 128 + j + 0] * Wout[(j + 0) * 64 + n];
        s1 += W2[k * 128 + j + 1] * Wout[(j + 1) * 64 + n];
        s2 += W2[k * 128 + j + 2] * Wout[(j + 2) * 64 + n];
        s3 += W2[k * 128 + j + 3] * Wout[(j + 3) * 64 + n];
    }
    g_W2p[idx] = (s0 + s1) + (s2 + s3);
    if (idx < 64) {
        float t = bout[idx];
        float t0 = 0.f, t1 = 0.f;
        #pragma unroll 8
        for (int j = 0; j < 128; j += 2) {
            t0 += b2[j] * Wout[j * 64 + idx];
            t1 += b2[j + 1] * Wout[(j + 1) * 64 + idx];
        }
        g_b2p[idx] = t + t0 + t1;
    }
}

// ---------------------------------------------------------------------------
// Layer 1: 8 producer warps (gather) / 4 consumer warps (mma.sync bf16x3)
// (unchanged from round 7)
// ---------------------------------------------------------------------------
extern "C" __global__ void __launch_bounds__(NT1, 1)
sage_layer1(const float* __restrict__ x, const int* __restrict__ nidx,
            const float* __restrict__ W1, const float* __restrict__ b1)
{
    extern __shared__ char smem[];
    const uint32_t sb = smem_u32(smem);
    float* biass = (float*)(smem + L1_BIAS);

    const int tid = threadIdx.x;
    if (tid < 128) biass[tid] = b1[tid];

    for (int i = tid; i < 256 * 128; i += NT1) {
        const int k = i >> 7, n = i & 127;
        const float w = W1[(size_t)k * 128 + n];
        const float h = bfr(w);
        *(__nv_bfloat16*)(smem + L1_BHI + (n * KSTR + k) * 2) = __float2bfloat16_rn(w);
        *(__nv_bfloat16*)(smem + L1_BLO + (n * KSTR + k) * 2) = __float2bfloat16_rn(w - h);
    }
    __syncthreads();

    if (tid < 256) {
        // ============ PRODUCERS (warps 0-7) ============
        for (int i = 0, tile = blockIdx.x; tile < NTILES1; tile += gridDim.x, i++) {
            const int b = i & 1;
            if (i >= 2) BAR_SYNC(3 + b, NT1);
            char* Ahi = smem + L1_A0 + b * L1_ABUF;
            char* Alo = Ahi + L1_AHALF;
            const int node0 = tile * TILE1;

            #pragma unroll
            for (int it = 0; it < 4; it++) {
                const int lin = tid + it * 256;
                const int nn  = lin >> 5;
                const int d4  = lin & 31;
                const int node = node0 + nn;
                const int4* np = (const int4*)(nidx + (size_t)node * S);
                const int4 na = np[0], nb4 = np[1], nc = np[2], nd = np[3];
                const int nb[16] = {na.x, na.y, na.z, na.w, nb4.x, nb4.y, nb4.z, nb4.w,
                                    nc.x, nc.y, nc.z, nc.w, nd.x, nd.y, nd.z, nd.w};
                gather_split(x, nb, node, nn, d4, Ahi, Alo);
            }
            BAR_ARRIVE(1 + b, NT1);
        }
    } else {
        // ============ CONSUMERS (warps 8-11) ============
        const int w  = (tid - 256) >> 5;
        const int l  = tid & 31;
        const int qr = l >> 2, qc = l & 3;
        const int nbase = w * 32;

        for (int i = 0, tile = blockIdx.x; tile < NTILES1; tile += gridDim.x, i++) {
            const int b = i & 1;
            BAR_SYNC(1 + b, NT1);
            const uint32_t aHi = sb + L1_A0 + b * L1_ABUF;
            const uint32_t aLo = aHi + L1_AHALF;
            const int node0 = tile * TILE1;

            float acc[2][4][4];
            #pragma unroll
            for (int t = 0; t < 2; t++)
                #pragma unroll
                for (int j = 0; j < 4; j++)
                    #pragma unroll
                    for (int u = 0; u < 4; u++) acc[t][j][u] = 0.f;

            #pragma unroll 2
            for (int ks = 0; ks < 16; ks++) {
                const int k0 = ks * 16;
                uint32_t ah[2][4], al[2][4];
                #pragma unroll
                for (int t = 0; t < 2; t++) {
                    const uint32_t r0 = (uint32_t)(t * 16 + qr) * (KSTR * 2);
                    const uint32_t r1 = r0 + 8 * (KSTR * 2);
                    const uint32_t cA = (uint32_t)(k0 + 2 * qc) * 2;
                    ah[t][0] = lds32(aHi + r0 + cA);  ah[t][1] = lds32(aHi + r1 + cA);
                    ah[t][2] = lds32(aHi + r0 + cA + 16); ah[t][3] = lds32(aHi + r1 + cA + 16);
                    al[t][0] = lds32(aLo + r0 + cA);  al[t][1] = lds32(aLo + r1 + cA);
                    al[t][2] = lds32(aLo + r0 + cA + 16); al[t][3] = lds32(aLo + r1 + cA + 16);
                }
                uint32_t bh[4][2], bl[4][2];
                #pragma unroll
                for (int j = 0; j < 4; j++) {
                    const uint32_t nrow = (uint32_t)(nbase + j * 8 + qr) * (KSTR * 2);
                    const uint32_t cB = (uint32_t)(k0 + 2 * qc) * 2;
                    bh[j][0] = lds32(sb + L1_BHI + nrow + cB);
                    bh[j][1] = lds32(sb + L1_BHI + nrow + cB + 16);
                    bl[j][0] = lds32(sb + L1_BLO + nrow + cB);
                    bl[j][1] = lds32(sb + L1_BLO + nrow + cB + 16);
                }
                #pragma unroll
                for (int t = 0; t < 2; t++)
                    #pragma unroll
                    for (int j = 0; j < 4; j++) {
                        mma_bf16(acc[t][j], ah[t][0], ah[t][1], ah[t][2], ah[t][3],
                                 bh[j][0], bh[j][1]);
                        mma_bf16(acc[t][j], ah[t][0], ah[t][1], ah[t][2], ah[t][3],
                                 bl[j][0], bl[j][1]);
                        mma_bf16(acc[t][j], al[t][0], al[t][1], al[t][2], al[t][3],
                                 bh[j][0], bh[j][1]);
                    }
            }
            BAR_ARRIVE(3 + b, NT1);

            #pragma unroll
            for (int t = 0; t < 2; t++) {
                const int r0 = node0 + t * 16 + qr;
                #pragma unroll
                for (int j = 0; j < 4; j++) {
                    const int n = nbase + j * 8 + 2 * qc;
                    const float bi0 = biass[n], bi1 = biass[n + 1];
                    float2 v0, v1;
                    v0.x = fmaxf(acc[t][j][0] + bi0, 0.f);
                    v0.y = fmaxf(acc[t][j][1] + bi1, 0.f);
                    v1.x = fmaxf(acc[t][j][2] + bi0, 0.f);
                    v1.y = fmaxf(acc[t][j][3] + bi1, 0.f);
                    *(float2*)(g_h1 + (size_t)r0 * D + n) = v0;
                    *(float2*)(g_h1 + (size_t)(r0 + 8) * D + n) = v1;
                }
            }
        }
    }
}

// ---------------------------------------------------------------------------
// Layer 2: ONE 64-node tile per block (grid=128). All warps gather, sync,
// all warps MMA. out = concat(h1[b], max h1[neigh[b]]) @ W2p + b2p
// ---------------------------------------------------------------------------
extern "C" __global__ void __launch_bounds__(NT2, 1)
sage_layer2(const int* __restrict__ nidx, const int* __restrict__ batch,
            float* __restrict__ out)
{
    extern __shared__ char smem[];
    const uint32_t sb = smem_u32(smem);
    float* biass = (float*)(smem + L2_BIAS);

    const int tid = threadIdx.x;
    if (tid < 64) biass[tid] = g_b2p[tid];

    // stage W2p split+transposed: B[n][k] = W2p[k][n]
    for (int i = tid; i < 256 * 64; i += NT2) {
        const int k = i >> 6, n = i & 63;
        const float w = g_W2p[i];
        const float h = bfr(w);
        *(__nv_bfloat16*)(smem + L2_BHI + (n * KSTR + k) * 2) = __float2bfloat16_rn(w);
        *(__nv_bfloat16*)(smem + L2_BLO + (n * KSTR + k) * 2) = __float2bfloat16_rn(w - h);
    }

    // ---- gather: 64 nodes x 32 d4 = 2048 items, 8 per thread ----
    char* Ahi = smem + L2_AHI;
    char* Alo = smem + L2_ALO;
    const int pos0 = blockIdx.x * TILE2;
    #pragma unroll
    for (int it = 0; it < 8; it++) {
        const int lin = tid + it * NT2;      // 0..2047
        const int nn  = lin >> 5;            // node 0..63 (warp-uniform)
        const int d4  = lin & 31;
        const int bnode = __ldg(batch + pos0 + nn);
        const int4* np = (const int4*)(nidx + (size_t)bnode * S);
        const int4 na = np[0], nb4 = np[1], nc = np[2], nd = np[3];
        const int nb[16] = {na.x, na.y, na.z, na.w, nb4.x, nb4.y, nb4.z, nb4.w,
                            nc.x, nc.y, nc.z, nc.w, nd.x, nd.y, nd.z, nd.w};
        gather_split(g_h1, nb, bnode, nn, d4, Ahi, Alo);
    }
    __syncthreads();

    // ---- MMA: 8 warps; warp w -> m-tile (w>>1), n-half (w&1) ----
    const int w  = tid >> 5;
    const int l  = tid & 31;
    const int qr = l >> 2, qc = l & 3;
    const int mt = w >> 1;            // 0..3 (16 rows each)
    const int nbase = (w & 1) * 32;   // 4 n-tiles of 8

    const uint32_t aHi = sb + L2_AHI;
    const uint32_t aLo = sb + L2_ALO;

    float acc[4][4];
    #pragma unroll
    for (int j = 0; j < 4; j++)
        #pragma unroll
        for (int u = 0; u < 4; u++) acc[j][u] = 0.f;

    #pragma unroll 2
    for (int ks = 0; ks < 16; ks++) {
        const int k0 = ks * 16;
        uint32_t ah[4], al[4];
        {
            const uint32_t r0 = (uint32_t)(mt * 16 + qr) * (KSTR * 2);
            const uint32_t r1 = r0 + 8 * (KSTR * 2);
            const uint32_t cA = (uint32_t)(k0 + 2 * qc) * 2;
            ah[0] = lds32(aHi + r0 + cA);      ah[1] = lds32(aHi + r1 + cA);
            ah[2] = lds32(aHi + r0 + cA + 16); ah[3] = lds32(aHi + r1 + cA + 16);
            al[0] = lds32(aLo + r0 + cA);      al[1] = lds32(aLo + r1 + cA);
            al[2] = lds32(aLo + r0 + cA + 16); al[3] = lds32(aLo + r1 + cA + 16);
        }
        uint32_t bh[4][2], bl[4][2];
        #pragma unroll
        for (int j = 0; j < 4; j++) {
            const uint32_t nrow = (uint32_t)(nbase + j * 8 + qr) * (KSTR * 2);
            const uint32_t cB = (uint32_t)(k0 + 2 * qc) * 2;
            bh[j][0] = lds32(sb + L2_BHI + nrow + cB);
            bh[j][1] = lds32(sb + L2_BHI + nrow + cB + 16);
            bl[j][0] = lds32(sb + L2_BLO + nrow + cB);
            bl[j][1] = lds32(sb + L2_BLO + nrow + cB + 16);
        }
        #pragma unroll
        for (int j = 0; j < 4; j++) {
            mma_bf16(acc[j], ah[0], ah[1], ah[2], ah[3], bh[j][0], bh[j][1]);
            mma_bf16(acc[j], ah[0], ah[1], ah[2], ah[3], bl[j][0], bl[j][1]);
            mma_bf16(acc[j], al[0], al[1], al[2], al[3], bh[j][0], bh[j][1]);
        }
    }

    // ---- epilogue: bias (no relu) -> out ----
    const int r0 = pos0 + mt * 16 + qr;
    #pragma unroll
    for (int j = 0; j < 4; j++) {
        const int n = nbase + j * 8 + 2 * qc;
        const float bi0 = biass[n], bi1 = biass[n + 1];
        float2 v0, v1;
        v0.x = acc[j][0] + bi0; v0.y = acc[j][1] + bi1;
        v1.x = acc[j][2] + bi0; v1.y = acc[j][3] + bi1;
        *(float2*)(out + (size_t)r0 * 64 + n) = v0;
        *(float2*)(out + (size_t)(r0 + 8) * 64 + n) = v1;
    }
}

// ---------------------------------------------------------------------------
extern "C" void kernel_launch(void* const* d_in, const int* in_sizes, int n_in,
                              void* d_out, int out_size)
{
    const float* x    = (const float*)d_in[0];
    const int*   nidx = (const int*)  d_in[1];
    const int*   batch= (const int*)  d_in[2];
    const float* W1   = (const float*)d_in[3];
    const float* b1   = (const float*)d_in[4];
    const float* W2   = (const float*)d_in[5];
    const float* b2   = (const float*)d_in[6];
    const float* Wout = (const float*)d_in[7];
    const float* bout = (const float*)d_in[8];
    float* out = (float*)d_out;

    cudaFuncSetAttribute((const void*)sage_layer1,
                         cudaFuncAttributeMaxDynamicSharedMemorySize, SMEM1_SZ);
    cudaFuncSetAttribute((const void*)sage_layer2,
                         cudaFuncAttributeMaxDynamicSharedMemorySize, SMEM2_SZ);

    prep_w2p<<<128, 128>>>(W2, b2, Wout, bout);
    sage_layer1<<<152, NT1, SMEM1_SZ>>>(x, nidx, W1, b1);
    sage_layer2<<<128, NT2, SMEM2_SZ>>>(nidx, batch, out);
}

// round 9
// speedup vs baseline: 6.3754x; 1.0337x over previous
#include <cuda_runtime.h>
#include <cuda_bf16.h>
#include <cstdint>

#define NNODES 100000
#define D      128
#define S      16
#define NBATCH 8192
#define NT1    512
#define NP1    384                   // producer threads (12 warps)

#define TILE1  32
#define KSTR   264                   // bf16 row stride (256 + 8 pad)

// ---- layer-1 smem offsets ----
#define L1_BHI   0
#define L1_BLO   67584
#define L1_A0    135168
#define L1_ABUF  33792
#define L1_AHALF 16896
#define L1_BIAS  202752
#define SMEM1_SZ 203264

// ---- layer-2 smem offsets (single 64-node tile) ----
#define L2_BHI   0
#define L2_BLO   33792
#define L2_AHI   67584
#define L2_ALO   101376
#define L2_BIAS  135168
#define SMEM2_SZ 135424
#define NT2      256
#define TILE2    64

__device__ float g_h1[(size_t)NNODES * D];
__device__ float g_W2p[256 * 64];
__device__ float g_b2p[64];
__device__ unsigned char g_mark[NNODES];
__device__ int  g_list[NNODES];
__device__ int  g_cnt;

// ---------------- helpers ----------------
__device__ __forceinline__ uint32_t pbf2(float lo, float hi) {
    uint32_t r;
    asm("cvt.rn.bf16x2.f32 %0, %1, %2;" : "=r"(r) : "f"(hi), "f"(lo));
    return r;
}
__device__ __forceinline__ float bfr(float f) {
    return __bfloat162float(__float2bfloat16_rn(f));
}
__device__ __forceinline__ uint32_t lds32(uint32_t a) {
    uint32_t v; asm volatile("ld.shared.b32 %0, [%1];" : "=r"(v) : "r"(a)); return v;
}
__device__ __forceinline__ uint32_t smem_u32(const void* p) {
    uint32_t a;
    asm("{ .reg .u64 t; cvta.to.shared.u64 t, %1; cvt.u32.u64 %0, t; }"
        : "=r"(a) : "l"(p));
    return a;
}
__device__ __forceinline__ void mma_bf16(float c[4], uint32_t a0, uint32_t a1,
                                         uint32_t a2, uint32_t a3,
                                         uint32_t b0, uint32_t b1) {
    asm volatile(
        "mma.sync.aligned.m16n8k16.row.col.f32.bf16.bf16.f32 "
        "{%0,%1,%2,%3}, {%4,%5,%6,%7}, {%8,%9}, {%0,%1,%2,%3};"
        : "+f"(c[0]), "+f"(c[1]), "+f"(c[2]), "+f"(c[3])
        : "r"(a0), "r"(a1), "r"(a2), "r"(a3), "r"(b0), "r"(b1));
}

#define BAR_SYNC(id, n)   asm volatile("bar.sync %0, %1;"   :: "r"(id), "r"(n) : "memory")
#define BAR_ARRIVE(id, n) asm volatile("bar.arrive %0, %1;" :: "r"(id), "r"(n) : "memory")

__device__ __forceinline__ void gather_split(
    const float* __restrict__ src, const int* nb, int node, int nn, int d4,
    char* Ahi, char* Alo)
{
    const float4 self = *((const float4*)(src + (size_t)node * D) + d4);
    float4 m = *((const float4*)(src + (size_t)nb[0] * D) + d4);
    #pragma unroll
    for (int s = 1; s < S; s++) {
        float4 v = *((const float4*)(src + (size_t)nb[s] * D) + d4);
        m.x = fmaxf(m.x, v.x); m.y = fmaxf(m.y, v.y);
        m.z = fmaxf(m.z, v.z); m.w = fmaxf(m.w, v.w);
    }
    const int ks = d4 * 4;
    const int ka = D + ks;
    uint2 v;
    v.x = pbf2(self.x, self.y); v.y = pbf2(self.z, self.w);
    *(uint2*)(Ahi + (nn * KSTR + ks) * 2) = v;
    v.x = pbf2(self.x - bfr(self.x), self.y - bfr(self.y));
    v.y = pbf2(self.z - bfr(self.z), self.w - bfr(self.w));
    *(uint2*)(Alo + (nn * KSTR + ks) * 2) = v;
    v.x = pbf2(m.x, m.y); v.y = pbf2(m.z, m.w);
    *(uint2*)(Ahi + (nn * KSTR + ka) * 2) = v;
    v.x = pbf2(m.x - bfr(m.x), m.y - bfr(m.y));
    v.y = pbf2(m.z - bfr(m.z), m.w - bfr(m.w));
    *(uint2*)(Alo + (nn * KSTR + ka) * 2) = v;
}

// ---------------------------------------------------------------------------
// mark: frontier = batch ∪ neigh(batch)
// ---------------------------------------------------------------------------
extern "C" __global__ void __launch_bounds__(128, 1)
mark_frontier(const int* __restrict__ batch, const int* __restrict__ nidx)
{
    const int i = blockIdx.x * 128 + threadIdx.x;   // 0..8191
    const int b = __ldg(batch + i);
    g_mark[b] = 1;
    const int4* np = (const int4*)(nidx + (size_t)b * S);
    const int4 a = np[0], c = np[1], d = np[2], e = np[3];
    g_mark[a.x] = 1; g_mark[a.y] = 1; g_mark[a.z] = 1; g_mark[a.w] = 1;
    g_mark[c.x] = 1; g_mark[c.y] = 1; g_mark[c.z] = 1; g_mark[c.w] = 1;
    g_mark[d.x] = 1; g_mark[d.y] = 1; g_mark[d.z] = 1; g_mark[d.w] = 1;
    g_mark[e.x] = 1; g_mark[e.y] = 1; g_mark[e.z] = 1; g_mark[e.w] = 1;
}

// ---------------------------------------------------------------------------
// compact: list of marked nodes (warp-aggregated atomics; order irrelevant)
// ---------------------------------------------------------------------------
extern "C" __global__ void __launch_bounds__(256, 1)
compact_frontier()
{
    const int i = blockIdx.x * 256 + threadIdx.x;
    const bool m = (i < NNODES) && (g_mark[i] != 0);
    const unsigned mask = __ballot_sync(0xFFFFFFFFu, m);
    const int lane = threadIdx.x & 31;
    int base = 0;
    if (lane == 0 && mask) base = atomicAdd(&g_cnt, __popc(mask));
    base = __shfl_sync(0xFFFFFFFFu, base, 0);
    if (m) g_list[base + __popc(mask & ((1u << lane) - 1))] = i;
}

// ---------------------------------------------------------------------------
// prep: W2p = W2 @ Wout (Wout staged in smem) ; b2p = b2 @ Wout + bout
// ---------------------------------------------------------------------------
extern "C" __global__ void __launch_bounds__(256, 1)
prep_w2p(const float* __restrict__ W2, const float* __restrict__ b2,
         const float* __restrict__ Wout, const float* __restrict__ bout)
{
    __shared__ float Wo[128 * 64];
    const int tid = threadIdx.x;
    for (int i = tid; i < 128 * 64 / 4; i += 256)
        ((float4*)Wo)[i] = ((const float4*)Wout)[i];
    __syncthreads();

    const int k = blockIdx.x * 4 + (tid >> 6);   // 0..255
    const int n = tid & 63;
    const float* w2r = W2 + k * 128;
    float s0 = 0.f, s1 = 0.f, s2 = 0.f, s3 = 0.f;
    #pragma unroll 8
    for (int j = 0; j < 128; j += 4) {
        s0 += w2r[j + 0] * Wo[(j + 0) * 64 + n];
        s1 += w2r[j + 1] * Wo[(j + 1) * 64 + n];
        s2 += w2r[j + 2] * Wo[(j + 2) * 64 + n];
        s3 += w2r[j + 3] * Wo[(j + 3) * 64 + n];
    }
    g_W2p[k * 64 + n] = (s0 + s1) + (s2 + s3);

    if (blockIdx.x == 0 && tid < 64) {
        float t = bout[tid];
        #pragma unroll 8
        for (int j = 0; j < 128; j++) t += b2[j] * Wo[j * 64 + tid];
        g_b2p[tid] = t;
    }
}

// ---------------------------------------------------------------------------
// Layer 1 over the compacted frontier: 12 producer / 4 consumer warps.
// ---------------------------------------------------------------------------
extern "C" __global__ void __launch_bounds__(NT1, 1)
sage_layer1(const float* __restrict__ x, const int* __restrict__ nidx,
            const float* __restrict__ W1, const float* __restrict__ b1)
{
    extern __shared__ char smem[];
    const uint32_t sb = smem_u32(smem);
    float* biass = (float*)(smem + L1_BIAS);

    const int tid = threadIdx.x;
    if (tid < 128) biass[tid] = b1[tid];

    for (int i = tid; i < 256 * 128; i += NT1) {
        const int k = i >> 7, n = i & 127;
        const float w = W1[(size_t)k * 128 + n];
        const float h = bfr(w);
        *(__nv_bfloat16*)(smem + L1_BHI + (n * KSTR + k) * 2) = __float2bfloat16_rn(w);
        *(__nv_bfloat16*)(smem + L1_BLO + (n * KSTR + k) * 2) = __float2bfloat16_rn(w - h);
    }
    __syncthreads();

    const int cnt = *(const volatile int*)&g_cnt;
    const int ntiles = (cnt + TILE1 - 1) / TILE1;

    if (tid < NP1) {
        // ============ PRODUCERS (warps 0-11) ============
        for (int i = 0, tile = blockIdx.x; tile < ntiles; tile += gridDim.x, i++) {
            const int b = i & 1;
            if (i >= 2) BAR_SYNC(3 + b, NT1);
            char* Ahi = smem + L1_A0 + b * L1_ABUF;
            char* Alo = Ahi + L1_AHALF;
            const int slot0 = tile * TILE1;

            for (int lin = tid; lin < TILE1 * 32; lin += NP1) {
                const int nn  = lin >> 5;            // warp-uniform
                const int d4  = lin & 31;
                const int node = g_list[min(slot0 + nn, cnt - 1)];
                const int4* np = (const int4*)(nidx + (size_t)node * S);
                const int4 na = np[0], nb4 = np[1], nc = np[2], nd = np[3];
                const int nb[16] = {na.x, na.y, na.z, na.w, nb4.x, nb4.y, nb4.z, nb4.w,
                                    nc.x, nc.y, nc.z, nc.w, nd.x, nd.y, nd.z, nd.w};
                gather_split(x, nb, node, nn, d4, Ahi, Alo);
            }
            BAR_ARRIVE(1 + b, NT1);
        }
    } else {
        // ============ CONSUMERS (warps 12-15) ============
        const int w  = (tid - NP1) >> 5;
        const int l  = tid & 31;
        const int qr = l >> 2, qc = l & 3;
        const int nbase = w * 32;

        for (int i = 0, tile = blockIdx.x; tile < ntiles; tile += gridDim.x, i++) {
            const int b = i & 1;
            BAR_SYNC(1 + b, NT1);
            const uint32_t aHi = sb + L1_A0 + b * L1_ABUF;
            const uint32_t aLo = aHi + L1_AHALF;
            const int slot0 = tile * TILE1;

            float acc[2][4][4];
            #pragma unroll
            for (int t = 0; t < 2; t++)
                #pragma unroll
                for (int j = 0; j < 4; j++)
                    #pragma unroll
                    for (int u = 0; u < 4; u++) acc[t][j][u] = 0.f;

            #pragma unroll 2
            for (int ks = 0; ks < 16; ks++) {
                const int k0 = ks * 16;
                uint32_t ah[2][4], al[2][4];
                #pragma unroll
                for (int t = 0; t < 2; t++) {
                    const uint32_t r0 = (uint32_t)(t * 16 + qr) * (KSTR * 2);
                    const uint32_t r1 = r0 + 8 * (KSTR * 2);
                    const uint32_t cA = (uint32_t)(k0 + 2 * qc) * 2;
                    ah[t][0] = lds32(aHi + r0 + cA);  ah[t][1] = lds32(aHi + r1 + cA);
                    ah[t][2] = lds32(aHi + r0 + cA + 16); ah[t][3] = lds32(aHi + r1 + cA + 16);
                    al[t][0] = lds32(aLo + r0 + cA);  al[t][1] = lds32(aLo + r1 + cA);
                    al[t][2] = lds32(aLo + r0 + cA + 16); al[t][3] = lds32(aLo + r1 + cA + 16);
                }
                uint32_t bh[4][2], bl[4][2];
                #pragma unroll
                for (int j = 0; j < 4; j++) {
                    const uint32_t nrow = (uint32_t)(nbase + j * 8 + qr) * (KSTR * 2);
                    const uint32_t cB = (uint32_t)(k0 + 2 * qc) * 2;
                    bh[j][0] = lds32(sb + L1_BHI + nrow + cB);
                    bh[j][1] = lds32(sb + L1_BHI + nrow + cB + 16);
                    bl[j][0] = lds32(sb + L1_BLO + nrow + cB);
                    bl[j][1] = lds32(sb + L1_BLO + nrow + cB + 16);
                }
                #pragma unroll
                for (int t = 0; t < 2; t++)
                    #pragma unroll
                    for (int j = 0; j < 4; j++) {
                        mma_bf16(acc[t][j], ah[t][0], ah[t][1], ah[t][2], ah[t][3],
                                 bh[j][0], bh[j][1]);
                        mma_bf16(acc[t][j], ah[t][0], ah[t][1], ah[t][2], ah[t][3],
                                 bl[j][0], bl[j][1]);
                        mma_bf16(acc[t][j], al[t][0], al[t][1], al[t][2], al[t][3],
                                 bh[j][0], bh[j][1]);
                    }
            }
            BAR_ARRIVE(3 + b, NT1);

            #pragma unroll
            for (int t = 0; t < 2; t++) {
                const int nodeA = g_list[min(slot0 + t * 16 + qr, cnt - 1)];
                const int nodeB = g_list[min(slot0 + t * 16 + qr + 8, cnt - 1)];
                #pragma unroll
                for (int j = 0; j < 4; j++) {
                    const int n = nbase + j * 8 + 2 * qc;
                    const float bi0 = biass[n], bi1 = biass[n + 1];
                    float2 v0, v1;
                    v0.x = fmaxf(acc[t][j][0] + bi0, 0.f);
                    v0.y = fmaxf(acc[t][j][1] + bi1, 0.f);
                    v1.x = fmaxf(acc[t][j][2] + bi0, 0.f);
                    v1.y = fmaxf(acc[t][j][3] + bi1, 0.f);
                    *(float2*)(g_h1 + (size_t)nodeA * D + n) = v0;
                    *(float2*)(g_h1 + (size_t)nodeB * D + n) = v1;
                }
            }
        }
    }
}

// ---------------------------------------------------------------------------
// Layer 2: one 64-node tile per block (grid=128), unchanged from round 8.
// ---------------------------------------------------------------------------
extern "C" __global__ void __launch_bounds__(NT2, 1)
sage_layer2(const int* __restrict__ nidx, const int* __restrict__ batch,
            float* __restrict__ out)
{
    extern __shared__ char smem[];
    const uint32_t sb = smem_u32(smem);
    float* biass = (float*)(smem + L2_BIAS);

    const int tid = threadIdx.x;
    if (tid < 64) biass[tid] = g_b2p[tid];

    for (int i = tid; i < 256 * 64; i += NT2) {
        const int k = i >> 6, n = i & 63;
        const float w = g_W2p[i];
        const float h = bfr(w);
        *(__nv_bfloat16*)(smem + L2_BHI + (n * KSTR + k) * 2) = __float2bfloat16_rn(w);
        *(__nv_bfloat16*)(smem + L2_BLO + (n * KSTR + k) * 2) = __float2bfloat16_rn(w - h);
    }

    char* Ahi = smem + L2_AHI;
    char* Alo = smem + L2_ALO;
    const int pos0 = blockIdx.x * TILE2;
    #pragma unroll
    for (int it = 0; it < 8; it++) {
        const int lin = tid + it * NT2;
        const int nn  = lin >> 5;
        const int d4  = lin & 31;
        const int bnode = __ldg(batch + pos0 + nn);
        const int4* np = (const int4*)(nidx + (size_t)bnode * S);
        const int4 na = np[0], nb4 = np[1], nc = np[2], nd = np[3];
        const int nb[16] = {na.x, na.y, na.z, na.w, nb4.x, nb4.y, nb4.z, nb4.w,
                            nc.x, nc.y, nc.z, nc.w, nd.x, nd.y, nd.z, nd.w};
        gather_split(g_h1, nb, bnode, nn, d4, Ahi, Alo);
    }
    __syncthreads();

    const int w  = tid >> 5;
    const int l  = tid & 31;
    const int qr = l >> 2, qc = l & 3;
    const int mt = w >> 1;
    const int nbase = (w & 1) * 32;

    const uint32_t aHi = sb + L2_AHI;
    const uint32_t aLo = sb + L2_ALO;

    float acc[4][4];
    #pragma unroll
    for (int j = 0; j < 4; j++)
        #pragma unroll
        for (int u = 0; u < 4; u++) acc[j][u] = 0.f;

    #pragma unroll 2
    for (int ks = 0; ks < 16; ks++) {
        const int k0 = ks * 16;
        uint32_t ah[4], al[4];
        {
            const uint32_t r0 = (uint32_t)(mt * 16 + qr) * (KSTR * 2);
            const uint32_t r1 = r0 + 8 * (KSTR * 2);
            const uint32_t cA = (uint32_t)(k0 + 2 * qc) * 2;
            ah[0] = lds32(aHi + r0 + cA);      ah[1] = lds32(aHi + r1 + cA);
            ah[2] = lds32(aHi + r0 + cA + 16); ah[3] = lds32(aHi + r1 + cA + 16);
            al[0] = lds32(aLo + r0 + cA);      al[1] = lds32(aLo + r1 + cA);
            al[2] = lds32(aLo + r0 + cA + 16); al[3] = lds32(aLo + r1 + cA + 16);
        }
        uint32_t bh[4][2], bl[4][2];
        #pragma unroll
        for (int j = 0; j < 4; j++) {
            const uint32_t nrow = (uint32_t)(nbase + j * 8 + qr) * (KSTR * 2);
            const uint32_t cB = (uint32_t)(k0 + 2 * qc) * 2;
            bh[j][0] = lds32(sb + L2_BHI + nrow + cB);
            bh[j][1] = lds32(sb + L2_BHI + nrow + cB + 16);
            bl[j][0] = lds32(sb + L2_BLO + nrow + cB);
            bl[j][1] = lds32(sb + L2_BLO + nrow + cB + 16);
        }
        #pragma unroll
        for (int j = 0; j < 4; j++) {
            mma_bf16(acc[j], ah[0], ah[1], ah[2], ah[3], bh[j][0], bh[j][1]);
            mma_bf16(acc[j], ah[0], ah[1], ah[2], ah[3], bl[j][0], bl[j][1]);
            mma_bf16(acc[j], al[0], al[1], al[2], al[3], bh[j][0], bh[j][1]);
        }
    }

    const int r0 = pos0 + mt * 16 + qr;
    #pragma unroll
    for (int j = 0; j < 4; j++) {
        const int n = nbase + j * 8 + 2 * qc;
        const float bi0 = biass[n], bi1 = biass[n + 1];
        float2 v0, v1;
        v0.x = acc[j][0] + bi0; v0.y = acc[j][1] + bi1;
        v1.x = acc[j][2] + bi0; v1.y = acc[j][3] + bi1;
        *(float2*)(out + (size_t)r0 * 64 + n) = v0;
        *(float2*)(out + (size_t)(r0 + 8) * 64 + n) = v1;
    }
}

// ---------------------------------------------------------------------------
extern "C" void kernel_launch(void* const* d_in, const int* in_sizes, int n_in,
                              void* d_out, int out_size)
{
    const float* x    = (const float*)d_in[0];
    const int*   nidx = (const int*)  d_in[1];
    const int*   batch= (const int*)  d_in[2];
    const float* W1   = (const float*)d_in[3];
    const float* b1   = (const float*)d_in[4];
    const float* W2   = (const float*)d_in[5];
    const float* b2   = (const float*)d_in[6];
    const float* Wout = (const float*)d_in[7];
    const float* bout = (const float*)d_in[8];
    float* out = (float*)d_out;

    cudaFuncSetAttribute((const void*)sage_layer1,
                         cudaFuncAttributeMaxDynamicSharedMemorySize, SMEM1_SZ);
    cudaFuncSetAttribute((const void*)sage_layer2,
                         cudaFuncAttributeMaxDynamicSharedMemorySize, SMEM2_SZ);

    void* p_mark; void* p_cnt;
    cudaGetSymbolAddress(&p_mark, g_mark);
    cudaGetSymbolAddress(&p_cnt,  g_cnt);
    cudaMemsetAsync(p_mark, 0, NNODES);
    cudaMemsetAsync(p_cnt,  0, sizeof(int));

    mark_frontier<<<NBATCH / 128, 128>>>(batch, nidx);
    compact_frontier<<<(NNODES + 255) / 256, 256>>>();
    prep_w2p<<<64, 256>>>(W2, b2, Wout, bout);
    sage_layer1<<<152, NT1, SMEM1_SZ>>>(x, nidx, W1, b1);
    sage_layer2<<<128, NT2, SMEM2_SZ>>>(nidx, batch, out);
}

// round 10
// speedup vs baseline: 6.6666x; 1.0457x over previous
#include <cuda_runtime.h>
#include <cuda_bf16.h>
#include <cstdint>

#define NNODES 100000
#define D      128
#define S      16
#define NBATCH 8192
#define NT1    768
#define NP1    512                   // producer threads (16 warps)

#define TILE1  32
#define KSTR   264                   // bf16 row stride (256 + 8 pad)

// ---- layer-1 smem offsets ----
#define L1_BHI   0
#define L1_BLO   67584
#define L1_A0    135168
#define L1_ABUF  33792
#define L1_AHALF 16896
#define L1_BIAS  202752
#define SMEM1_SZ 203264

// ---- layer-2 smem offsets (single 64-node tile) ----
#define L2_BHI   0
#define L2_BLO   33792
#define L2_AHI   67584
#define L2_ALO   101376
#define L2_BIAS  135168
#define SMEM2_SZ 135424
#define NT2      512
#define TILE2    64

__device__ float g_h1[(size_t)NNODES * D];
__device__ float g_W2p[256 * 64];
__device__ float g_b2p[64];
__device__ unsigned char g_mark[NNODES];
__device__ int  g_list[NNODES];
__device__ int  g_cnt;

// ---------------- helpers ----------------
__device__ __forceinline__ uint32_t pbf2(float lo, float hi) {
    uint32_t r;
    asm("cvt.rn.bf16x2.f32 %0, %1, %2;" : "=r"(r) : "f"(hi), "f"(lo));
    return r;
}
__device__ __forceinline__ float bfr(float f) {
    return __bfloat162float(__float2bfloat16_rn(f));
}
__device__ __forceinline__ uint32_t lds32(uint32_t a) {
    uint32_t v; asm volatile("ld.shared.b32 %0, [%1];" : "=r"(v) : "r"(a)); return v;
}
__device__ __forceinline__ uint32_t smem_u32(const void* p) {
    uint32_t a;
    asm("{ .reg .u64 t; cvta.to.shared.u64 t, %1; cvt.u32.u64 %0, t; }"
        : "=r"(a) : "l"(p));
    return a;
}
__device__ __forceinline__ void mma_bf16(float c[4], uint32_t a0, uint32_t a1,
                                         uint32_t a2, uint32_t a3,
                                         uint32_t b0, uint32_t b1) {
    asm volatile(
        "mma.sync.aligned.m16n8k16.row.col.f32.bf16.bf16.f32 "
        "{%0,%1,%2,%3}, {%4,%5,%6,%7}, {%8,%9}, {%0,%1,%2,%3};"
        : "+f"(c[0]), "+f"(c[1]), "+f"(c[2]), "+f"(c[3])
        : "r"(a0), "r"(a1), "r"(a2), "r"(a3), "r"(b0), "r"(b1));
}

#define BAR_SYNC(id, n)   asm volatile("bar.sync %0, %1;"   :: "r"(id), "r"(n) : "memory")
#define BAR_ARRIVE(id, n) asm volatile("bar.arrive %0, %1;" :: "r"(id), "r"(n) : "memory")

__device__ __forceinline__ void gather_split(
    const float* __restrict__ src, const int* nb, int node, int nn, int d4,
    char* Ahi, char* Alo)
{
    const float4 self = *((const float4*)(src + (size_t)node * D) + d4);
    float4 m = *((const float4*)(src + (size_t)nb[0] * D) + d4);
    #pragma unroll
    for (int s = 1; s < S; s++) {
        float4 v = *((const float4*)(src + (size_t)nb[s] * D) + d4);
        m.x = fmaxf(m.x, v.x); m.y = fmaxf(m.y, v.y);
        m.z = fmaxf(m.z, v.z); m.w = fmaxf(m.w, v.w);
    }
    const int ks = d4 * 4;
    const int ka = D + ks;
    uint2 v;
    v.x = pbf2(self.x, self.y); v.y = pbf2(self.z, self.w);
    *(uint2*)(Ahi + (nn * KSTR + ks) * 2) = v;
    v.x = pbf2(self.x - bfr(self.x), self.y - bfr(self.y));
    v.y = pbf2(self.z - bfr(self.z), self.w - bfr(self.w));
    *(uint2*)(Alo + (nn * KSTR + ks) * 2) = v;
    v.x = pbf2(m.x, m.y); v.y = pbf2(m.z, m.w);
    *(uint2*)(Ahi + (nn * KSTR + ka) * 2) = v;
    v.x = pbf2(m.x - bfr(m.x), m.y - bfr(m.y));
    v.y = pbf2(m.z - bfr(m.z), m.w - bfr(m.w));
    *(uint2*)(Alo + (nn * KSTR + ka) * 2) = v;
}

// ---------------------------------------------------------------------------
extern "C" __global__ void __launch_bounds__(128, 1)
mark_frontier(const int* __restrict__ batch, const int* __restrict__ nidx)
{
    const int i = blockIdx.x * 128 + threadIdx.x;
    const int b = __ldg(batch + i);
    g_mark[b] = 1;
    const int4* np = (const int4*)(nidx + (size_t)b * S);
    const int4 a = np[0], c = np[1], d = np[2], e = np[3];
    g_mark[a.x] = 1; g_mark[a.y] = 1; g_mark[a.z] = 1; g_mark[a.w] = 1;
    g_mark[c.x] = 1; g_mark[c.y] = 1; g_mark[c.z] = 1; g_mark[c.w] = 1;
    g_mark[d.x] = 1; g_mark[d.y] = 1; g_mark[d.z] = 1; g_mark[d.w] = 1;
    g_mark[e.x] = 1; g_mark[e.y] = 1; g_mark[e.z] = 1; g_mark[e.w] = 1;
}

extern "C" __global__ void __launch_bounds__(256, 1)
compact_frontier()
{
    const int i = blockIdx.x * 256 + threadIdx.x;
    const bool m = (i < NNODES) && (g_mark[i] != 0);
    const unsigned mask = __ballot_sync(0xFFFFFFFFu, m);
    const int lane = threadIdx.x & 31;
    int base = 0;
    if (lane == 0 && mask) base = atomicAdd(&g_cnt, __popc(mask));
    base = __shfl_sync(0xFFFFFFFFu, base, 0);
    if (m) g_list[base + __popc(mask & ((1u << lane) - 1))] = i;
}

extern "C" __global__ void __launch_bounds__(256, 1)
prep_w2p(const float* __restrict__ W2, const float* __restrict__ b2,
         const float* __restrict__ Wout, const float* __restrict__ bout)
{
    __shared__ float Wo[128 * 64];
    const int tid = threadIdx.x;
    for (int i = tid; i < 128 * 64 / 4; i += 256)
        ((float4*)Wo)[i] = ((const float4*)Wout)[i];
    __syncthreads();

    const int k = blockIdx.x * 4 + (tid >> 6);
    const int n = tid & 63;
    const float* w2r = W2 + k * 128;
    float s0 = 0.f, s1 = 0.f, s2 = 0.f, s3 = 0.f;
    #pragma unroll 8
    for (int j = 0; j < 128; j += 4) {
        s0 += w2r[j + 0] * Wo[(j + 0) * 64 + n];
        s1 += w2r[j + 1] * Wo[(j + 1) * 64 + n];
        s2 += w2r[j + 2] * Wo[(j + 2) * 64 + n];
        s3 += w2r[j + 3] * Wo[(j + 3) * 64 + n];
    }
    g_W2p[k * 64 + n] = (s0 + s1) + (s2 + s3);

    if (blockIdx.x == 0 && tid < 64) {
        float t = bout[tid];
        #pragma unroll 8
        for (int j = 0; j < 128; j++) t += b2[j] * Wo[j * 64 + tid];
        g_b2p[tid] = t;
    }
}

// ---------------------------------------------------------------------------
// Layer 1 over the compacted frontier: 16 producer / 8 consumer warps.
// ---------------------------------------------------------------------------
extern "C" __global__ void __launch_bounds__(NT1, 1)
sage_layer1(const float* __restrict__ x, const int* __restrict__ nidx,
            const float* __restrict__ W1, const float* __restrict__ b1)
{
    extern __shared__ char smem[];
    const uint32_t sb = smem_u32(smem);
    float* biass = (float*)(smem + L1_BIAS);

    const int tid = threadIdx.x;
    if (tid < 128) biass[tid] = b1[tid];

    for (int i = tid; i < 256 * 128; i += NT1) {
        const int k = i >> 7, n = i & 127;
        const float w = W1[(size_t)k * 128 + n];
        const float h = bfr(w);
        *(__nv_bfloat16*)(smem + L1_BHI + (n * KSTR + k) * 2) = __float2bfloat16_rn(w);
        *(__nv_bfloat16*)(smem + L1_BLO + (n * KSTR + k) * 2) = __float2bfloat16_rn(w - h);
    }
    __syncthreads();

    const int cnt = *(const volatile int*)&g_cnt;
    const int ntiles = (cnt + TILE1 - 1) / TILE1;

    if (tid < NP1) {
        // ============ PRODUCERS (warps 0-15): 2 items each ============
        for (int i = 0, tile = blockIdx.x; tile < ntiles; tile += gridDim.x, i++) {
            const int b = i & 1;
            if (i >= 2) BAR_SYNC(3 + b, NT1);
            char* Ahi = smem + L1_A0 + b * L1_ABUF;
            char* Alo = Ahi + L1_AHALF;
            const int slot0 = tile * TILE1;

            #pragma unroll
            for (int it = 0; it < 2; it++) {
                const int lin = tid + it * NP1;      // 0..1023
                const int nn  = lin >> 5;            // warp-uniform
                const int d4  = lin & 31;
                const int node = g_list[min(slot0 + nn, cnt - 1)];
                const int4* np = (const int4*)(nidx + (size_t)node * S);
                const int4 na = np[0], nb4 = np[1], nc = np[2], nd = np[3];
                const int nb[16] = {na.x, na.y, na.z, na.w, nb4.x, nb4.y, nb4.z, nb4.w,
                                    nc.x, nc.y, nc.z, nc.w, nd.x, nd.y, nd.z, nd.w};
                gather_split(x, nb, node, nn, d4, Ahi, Alo);
            }
            BAR_ARRIVE(1 + b, NT1);
        }
    } else {
        // ============ CONSUMERS (warps 16-23): m32 x n16 each ============
        const int w  = (tid - NP1) >> 5;    // 0..7
        const int l  = tid & 31;
        const int qr = l >> 2, qc = l & 3;
        const int nbase = w * 16;

        for (int i = 0, tile = blockIdx.x; tile < ntiles; tile += gridDim.x, i++) {
            const int b = i & 1;
            BAR_SYNC(1 + b, NT1);
            const uint32_t aHi = sb + L1_A0 + b * L1_ABUF;
            const uint32_t aLo = aHi + L1_AHALF;
            const int slot0 = tile * TILE1;

            float acc[2][2][4];
            #pragma unroll
            for (int t = 0; t < 2; t++)
                #pragma unroll
                for (int j = 0; j < 2; j++)
                    #pragma unroll
                    for (int u = 0; u < 4; u++) acc[t][j][u] = 0.f;

            #pragma unroll 2
            for (int ks = 0; ks < 16; ks++) {
                const int k0 = ks * 16;
                uint32_t ah[2][4], al[2][4];
                #pragma unroll
                for (int t = 0; t < 2; t++) {
                    const uint32_t r0 = (uint32_t)(t * 16 + qr) * (KSTR * 2);
                    const uint32_t r1 = r0 + 8 * (KSTR * 2);
                    const uint32_t cA = (uint32_t)(k0 + 2 * qc) * 2;
                    ah[t][0] = lds32(aHi + r0 + cA);  ah[t][1] = lds32(aHi + r1 + cA);
                    ah[t][2] = lds32(aHi + r0 + cA + 16); ah[t][3] = lds32(aHi + r1 + cA + 16);
                    al[t][0] = lds32(aLo + r0 + cA);  al[t][1] = lds32(aLo + r1 + cA);
                    al[t][2] = lds32(aLo + r0 + cA + 16); al[t][3] = lds32(aLo + r1 + cA + 16);
                }
                uint32_t bh[2][2], bl[2][2];
                #pragma unroll
                for (int j = 0; j < 2; j++) {
                    const uint32_t nrow = (uint32_t)(nbase + j * 8 + qr) * (KSTR * 2);
                    const uint32_t cB = (uint32_t)(k0 + 2 * qc) * 2;
                    bh[j][0] = lds32(sb + L1_BHI + nrow + cB);
                    bh[j][1] = lds32(sb + L1_BHI + nrow + cB + 16);
                    bl[j][0] = lds32(sb + L1_BLO + nrow + cB);
                    bl[j][1] = lds32(sb + L1_BLO + nrow + cB + 16);
                }
                #pragma unroll
                for (int t = 0; t < 2; t++)
                    #pragma unroll
                    for (int j = 0; j < 2; j++) {
                        mma_bf16(acc[t][j], ah[t][0], ah[t][1], ah[t][2], ah[t][3],
                                 bh[j][0], bh[j][1]);
                        mma_bf16(acc[t][j], ah[t][0], ah[t][1], ah[t][2], ah[t][3],
                                 bl[j][0], bl[j][1]);
                        mma_bf16(acc[t][j], al[t][0], al[t][1], al[t][2], al[t][3],
                                 bh[j][0], bh[j][1]);
                    }
            }
            BAR_ARRIVE(3 + b, NT1);

            #pragma unroll
            for (int t = 0; t < 2; t++) {
                const int nodeA = g_list[min(slot0 + t * 16 + qr, cnt - 1)];
                const int nodeB = g_list[min(slot0 + t * 16 + qr + 8, cnt - 1)];
                #pragma unroll
                for (int j = 0; j < 2; j++) {
                    const int n = nbase + j * 8 + 2 * qc;
                    const float bi0 = biass[n], bi1 = biass[n + 1];
                    float2 v0, v1;
                    v0.x = fmaxf(acc[t][j][0] + bi0, 0.f);
                    v0.y = fmaxf(acc[t][j][1] + bi1, 0.f);
                    v1.x = fmaxf(acc[t][j][2] + bi0, 0.f);
                    v1.y = fmaxf(acc[t][j][3] + bi1, 0.f);
                    *(float2*)(g_h1 + (size_t)nodeA * D + n) = v0;
                    *(float2*)(g_h1 + (size_t)nodeB * D + n) = v1;
                }
            }
        }
    }
}

// ---------------------------------------------------------------------------
// Layer 2: one 64-node tile per block (grid=128), 512 threads.
// ---------------------------------------------------------------------------
extern "C" __global__ void __launch_bounds__(NT2, 1)
sage_layer2(const int* __restrict__ nidx, const int* __restrict__ batch,
            float* __restrict__ out)
{
    extern __shared__ char smem[];
    const uint32_t sb = smem_u32(smem);
    float* biass = (float*)(smem + L2_BIAS);

    const int tid = threadIdx.x;
    if (tid < 64) biass[tid] = g_b2p[tid];

    for (int i = tid; i < 256 * 64; i += NT2) {
        const int k = i >> 6, n = i & 63;
        const float w = g_W2p[i];
        const float h = bfr(w);
        *(__nv_bfloat16*)(smem + L2_BHI + (n * KSTR + k) * 2) = __float2bfloat16_rn(w);
        *(__nv_bfloat16*)(smem + L2_BLO + (n * KSTR + k) * 2) = __float2bfloat16_rn(w - h);
    }

    char* Ahi = smem + L2_AHI;
    char* Alo = smem + L2_ALO;
    const int pos0 = blockIdx.x * TILE2;
    #pragma unroll
    for (int it = 0; it < 4; it++) {
        const int lin = tid + it * NT2;      // 0..2047
        const int nn  = lin >> 5;
        const int d4  = lin & 31;
        const int bnode = __ldg(batch + pos0 + nn);
        const int4* np = (const int4*)(nidx + (size_t)bnode * S);
        const int4 na = np[0], nb4 = np[1], nc = np[2], nd = np[3];
        const int nb[16] = {na.x, na.y, na.z, na.w, nb4.x, nb4.y, nb4.z, nb4.w,
                            nc.x, nc.y, nc.z, nc.w, nd.x, nd.y, nd.z, nd.w};
        gather_split(g_h1, nb, bnode, nn, d4, Ahi, Alo);
    }
    __syncthreads();

    // ---- MMA: 16 warps; warp w -> m-tile (w>>2), n-block (w&3)*16 ----
    const int w  = tid >> 5;
    const int l  = tid & 31;
    const int qr = l >> 2, qc = l & 3;
    const int mt = w >> 2;            // 0..3
    const int nbase = (w & 3) * 16;   // 2 n-tiles of 8

    const uint32_t aHi = sb + L2_AHI;
    const uint32_t aLo = sb + L2_ALO;

    float acc[2][4];
    #pragma unroll
    for (int j = 0; j < 2; j++)
        #pragma unroll
        for (int u = 0; u < 4; u++) acc[j][u] = 0.f;

    #pragma unroll 2
    for (int ks = 0; ks < 16; ks++) {
        const int k0 = ks * 16;
        uint32_t ah[4], al[4];
        {
            const uint32_t r0 = (uint32_t)(mt * 16 + qr) * (KSTR * 2);
            const uint32_t r1 = r0 + 8 * (KSTR * 2);
            const uint32_t cA = (uint32_t)(k0 + 2 * qc) * 2;
            ah[0] = lds32(aHi + r0 + cA);      ah[1] = lds32(aHi + r1 + cA);
            ah[2] = lds32(aHi + r0 + cA + 16); ah[3] = lds32(aHi + r1 + cA + 16);
            al[0] = lds32(aLo + r0 + cA);      al[1] = lds32(aLo + r1 + cA);
            al[2] = lds32(aLo + r0 + cA + 16); al[3] = lds32(aLo + r1 + cA + 16);
        }
        uint32_t bh[2][2], bl[2][2];
        #pragma unroll
        for (int j = 0; j < 2; j++) {
            const uint32_t nrow = (uint32_t)(nbase + j * 8 + qr) * (KSTR * 2);
            const uint32_t cB = (uint32_t)(k0 + 2 * qc) * 2;
            bh[j][0] = lds32(sb + L2_BHI + nrow + cB);
            bh[j][1] = lds32(sb + L2_BHI + nrow + cB + 16);
            bl[j][0] = lds32(sb + L2_BLO + nrow + cB);
            bl[j][1] = lds32(sb + L2_BLO + nrow + cB + 16);
        }
        #pragma unroll
        for (int j = 0; j < 2; j++) {
            mma_bf16(acc[j], ah[0], ah[1], ah[2], ah[3], bh[j][0], bh[j][1]);
            mma_bf16(acc[j], ah[0], ah[1], ah[2], ah[3], bl[j][0], bl[j][1]);
            mma_bf16(acc[j], al[0], al[1], al[2], al[3], bh[j][0], bh[j][1]);
        }
    }

    const int r0 = pos0 + mt * 16 + qr;
    #pragma unroll
    for (int j = 0; j < 2; j++) {
        const int n = nbase + j * 8 + 2 * qc;
        const float bi0 = biass[n], bi1 = biass[n + 1];
        float2 v0, v1;
        v0.x = acc[j][0] + bi0; v0.y = acc[j][1] + bi1;
        v1.x = acc[j][2] + bi0; v1.y = acc[j][3] + bi1;
        *(float2*)(out + (size_t)r0 * 64 + n) = v0;
        *(float2*)(out + (size_t)(r0 + 8) * 64 + n) = v1;
    }
}

// ---------------------------------------------------------------------------
extern "C" void kernel_launch(void* const* d_in, const int* in_sizes, int n_in,
                              void* d_out, int out_size)
{
    const float* x    = (const float*)d_in[0];
    const int*   nidx = (const int*)  d_in[1];
    const int*   batch= (const int*)  d_in[2];
    const float* W1   = (const float*)d_in[3];
    const float* b1   = (const float*)d_in[4];
    const float* W2   = (const float*)d_in[5];
    const float* b2   = (const float*)d_in[6];
    const float* Wout = (const float*)d_in[7];
    const float* bout = (const float*)d_in[8];
    float* out = (float*)d_out;

    cudaFuncSetAttribute((const void*)sage_layer1,
                         cudaFuncAttributeMaxDynamicSharedMemorySize, SMEM1_SZ);
    cudaFuncSetAttribute((const void*)sage_layer2,
                         cudaFuncAttributeMaxDynamicSharedMemorySize, SMEM2_SZ);

    void* p_mark; void* p_cnt;
    cudaGetSymbolAddress(&p_mark, g_mark);
    cudaGetSymbolAddress(&p_cnt,  g_cnt);
    cudaMemsetAsync(p_mark, 0, NNODES);
    cudaMemsetAsync(p_cnt,  0, sizeof(int));

    mark_frontier<<<NBATCH / 128, 128>>>(batch, nidx);
    compact_frontier<<<(NNODES + 255) / 256, 256>>>();
    prep_w2p<<<64, 256>>>(W2, b2, Wout, bout);
    sage_layer1<<<152, NT1, SMEM1_SZ>>>(x, nidx, W1, b1);
    sage_layer2<<<128, NT2, SMEM2_SZ>>>(nidx, batch, out);
}

// round 11
// speedup vs baseline: 6.6761x; 1.0014x over previous
#include <cuda_runtime.h>
#include <cuda_bf16.h>
#include <cstdint>

#define NNODES 100000
#define D      128
#define S      16
#define NBATCH 8192
#define NT1    1024
#define NP1    768                   // producer threads (24 warps)

#define TILE1  32
#define KSTR   264                   // bf16 row stride (256 + 8 pad)

// ---- layer-1 smem offsets ----
#define L1_BHI   0
#define L1_BLO   67584
#define L1_A0    135168
#define L1_ABUF  33792
#define L1_AHALF 16896
#define L1_BIAS  202752
#define SMEM1_SZ 203264

// ---- layer-2 smem offsets (32-node tile, 2 blocks/SM) ----
#define L2_BHI   0                   // 33792
#define L2_BLO   33792               // 33792
#define L2_AHI   67584               // 16896
#define L2_ALO   84480               // 16896
#define L2_BIAS  101376              // 256
#define SMEM2_SZ 101632
#define NT2      512
#define TILE2    32

__device__ float g_h1[(size_t)NNODES * D];
__device__ float g_W2p[256 * 64];
__device__ float g_b2p[64];
__device__ unsigned char g_mark[NNODES];
__device__ int  g_list[NNODES];
__device__ int  g_cnt;

// ---------------- helpers ----------------
__device__ __forceinline__ uint32_t pbf2(float lo, float hi) {
    uint32_t r;
    asm("cvt.rn.bf16x2.f32 %0, %1, %2;" : "=r"(r) : "f"(hi), "f"(lo));
    return r;
}
__device__ __forceinline__ float bfr(float f) {
    return __bfloat162float(__float2bfloat16_rn(f));
}
__device__ __forceinline__ uint32_t lds32(uint32_t a) {
    uint32_t v; asm volatile("ld.shared.b32 %0, [%1];" : "=r"(v) : "r"(a)); return v;
}
__device__ __forceinline__ uint32_t smem_u32(const void* p) {
    uint32_t a;
    asm("{ .reg .u64 t; cvta.to.shared.u64 t, %1; cvt.u32.u64 %0, t; }"
        : "=r"(a) : "l"(p));
    return a;
}
__device__ __forceinline__ void mma_bf16(float c[4], uint32_t a0, uint32_t a1,
                                         uint32_t a2, uint32_t a3,
                                         uint32_t b0, uint32_t b1) {
    asm volatile(
        "mma.sync.aligned.m16n8k16.row.col.f32.bf16.bf16.f32 "
        "{%0,%1,%2,%3}, {%4,%5,%6,%7}, {%8,%9}, {%0,%1,%2,%3};"
        : "+f"(c[0]), "+f"(c[1]), "+f"(c[2]), "+f"(c[3])
        : "r"(a0), "r"(a1), "r"(a2), "r"(a3), "r"(b0), "r"(b1));
}

#define BAR_SYNC(id, n)   asm volatile("bar.sync %0, %1;"   :: "r"(id), "r"(n) : "memory")
#define BAR_ARRIVE(id, n) asm volatile("bar.arrive %0, %1;" :: "r"(id), "r"(n) : "memory")

__device__ __forceinline__ void gather_split(
    const float* __restrict__ src, const int* nb, int node, int nn, int d4,
    char* Ahi, char* Alo)
{
    const float4 self = *((const float4*)(src + (size_t)node * D) + d4);
    float4 m = *((const float4*)(src + (size_t)nb[0] * D) + d4);
    #pragma unroll
    for (int s = 1; s < S; s++) {
        float4 v = *((const float4*)(src + (size_t)nb[s] * D) + d4);
        m.x = fmaxf(m.x, v.x); m.y = fmaxf(m.y, v.y);
        m.z = fmaxf(m.z, v.z); m.w = fmaxf(m.w, v.w);
    }
    const int ks = d4 * 4;
    const int ka = D + ks;
    uint2 v;
    v.x = pbf2(self.x, self.y); v.y = pbf2(self.z, self.w);
    *(uint2*)(Ahi + (nn * KSTR + ks) * 2) = v;
    v.x = pbf2(self.x - bfr(self.x), self.y - bfr(self.y));
    v.y = pbf2(self.z - bfr(self.z), self.w - bfr(self.w));
    *(uint2*)(Alo + (nn * KSTR + ks) * 2) = v;
    v.x = pbf2(m.x, m.y); v.y = pbf2(m.z, m.w);
    *(uint2*)(Ahi + (nn * KSTR + ka) * 2) = v;
    v.x = pbf2(m.x - bfr(m.x), m.y - bfr(m.y));
    v.y = pbf2(m.z - bfr(m.z), m.w - bfr(m.w));
    *(uint2*)(Alo + (nn * KSTR + ka) * 2) = v;
}

// ---------------------------------------------------------------------------
// fused: blocks 0-63 = prep (W2p = W2@Wout, b2p); blocks 64-127 = mark frontier
// ---------------------------------------------------------------------------
extern "C" __global__ void __launch_bounds__(256, 1)
mark_prep(const int* __restrict__ batch, const int* __restrict__ nidx,
          const float* __restrict__ W2, const float* __restrict__ b2,
          const float* __restrict__ Wout, const float* __restrict__ bout)
{
    __shared__ float Wo[128 * 64];
    const int tid = threadIdx.x;
    if (blockIdx.x < 64) {
        for (int i = tid; i < 128 * 64 / 4; i += 256)
            ((float4*)Wo)[i] = ((const float4*)Wout)[i];
        __syncthreads();

        const int k = blockIdx.x * 4 + (tid >> 6);
        const int n = tid & 63;
        const float* w2r = W2 + k * 128;
        float s0 = 0.f, s1 = 0.f, s2 = 0.f, s3 = 0.f;
        #pragma unroll 8
        for (int j = 0; j < 128; j += 4) {
            s0 += w2r[j + 0] * Wo[(j + 0) * 64 + n];
            s1 += w2r[j + 1] * Wo[(j + 1) * 64 + n];
            s2 += w2r[j + 2] * Wo[(j + 2) * 64 + n];
            s3 += w2r[j + 3] * Wo[(j + 3) * 64 + n];
        }
        g_W2p[k * 64 + n] = (s0 + s1) + (s2 + s3);

        if (blockIdx.x == 0 && tid < 64) {
            float t = bout[tid];
            #pragma unroll 8
            for (int j = 0; j < 128; j++) t += b2[j] * Wo[j * 64 + tid];
            g_b2p[tid] = t;
        }
    } else if (tid < 128) {
        const int i = (blockIdx.x - 64) * 128 + tid;    // 0..8191
        const int b = __ldg(batch + i);
        g_mark[b] = 1;
        const int4* np = (const int4*)(nidx + (size_t)b * S);
        const int4 a = np[0], c = np[1], d = np[2], e = np[3];
        g_mark[a.x] = 1; g_mark[a.y] = 1; g_mark[a.z] = 1; g_mark[a.w] = 1;
        g_mark[c.x] = 1; g_mark[c.y] = 1; g_mark[c.z] = 1; g_mark[c.w] = 1;
        g_mark[d.x] = 1; g_mark[d.y] = 1; g_mark[d.z] = 1; g_mark[d.w] = 1;
        g_mark[e.x] = 1; g_mark[e.y] = 1; g_mark[e.z] = 1; g_mark[e.w] = 1;
    }
}

extern "C" __global__ void __launch_bounds__(256, 1)
compact_frontier()
{
    const int i = blockIdx.x * 256 + threadIdx.x;
    const bool m = (i < NNODES) && (g_mark[i] != 0);
    const unsigned mask = __ballot_sync(0xFFFFFFFFu, m);
    const int lane = threadIdx.x & 31;
    int base = 0;
    if (lane == 0 && mask) base = atomicAdd(&g_cnt, __popc(mask));
    base = __shfl_sync(0xFFFFFFFFu, base, 0);
    if (m) g_list[base + __popc(mask & ((1u << lane) - 1))] = i;
}

// ---------------------------------------------------------------------------
// Layer 1 over the compacted frontier: 24 producer / 8 consumer warps.
// ---------------------------------------------------------------------------
extern "C" __global__ void __launch_bounds__(NT1, 1)
sage_layer1(const float* __restrict__ x, const int* __restrict__ nidx,
            const float* __restrict__ W1, const float* __restrict__ b1)
{
    extern __shared__ char smem[];
    const uint32_t sb = smem_u32(smem);
    float* biass = (float*)(smem + L1_BIAS);

    const int tid = threadIdx.x;
    if (tid < 128) biass[tid] = b1[tid];

    for (int i = tid; i < 256 * 128; i += NT1) {
        const int k = i >> 7, n = i & 127;
        const float w = W1[(size_t)k * 128 + n];
        const float h = bfr(w);
        *(__nv_bfloat16*)(smem + L1_BHI + (n * KSTR + k) * 2) = __float2bfloat16_rn(w);
        *(__nv_bfloat16*)(smem + L1_BLO + (n * KSTR + k) * 2) = __float2bfloat16_rn(w - h);
    }
    __syncthreads();

    const int cnt = *(const volatile int*)&g_cnt;
    const int ntiles = (cnt + TILE1 - 1) / TILE1;

    if (tid < NP1) {
        // ============ PRODUCERS (warps 0-23) ============
        for (int i = 0, tile = blockIdx.x; tile < ntiles; tile += gridDim.x, i++) {
            const int b = i & 1;
            if (i >= 2) BAR_SYNC(3 + b, NT1);
            char* Ahi = smem + L1_A0 + b * L1_ABUF;
            char* Alo = Ahi + L1_AHALF;
            const int slot0 = tile * TILE1;

            for (int lin = tid; lin < TILE1 * 32; lin += NP1) {
                const int nn  = lin >> 5;            // warp-uniform
                const int d4  = lin & 31;
                const int node = g_list[min(slot0 + nn, cnt - 1)];
                const int4* np = (const int4*)(nidx + (size_t)node * S);
                const int4 na = np[0], nb4 = np[1], nc = np[2], nd = np[3];
                const int nb[16] = {na.x, na.y, na.z, na.w, nb4.x, nb4.y, nb4.z, nb4.w,
                                    nc.x, nc.y, nc.z, nc.w, nd.x, nd.y, nd.z, nd.w};
                gather_split(x, nb, node, nn, d4, Ahi, Alo);
            }
            BAR_ARRIVE(1 + b, NT1);
        }
    } else {
        // ============ CONSUMERS (warps 24-31): m32 x n16 each ============
        const int w  = (tid - NP1) >> 5;    // 0..7
        const int l  = tid & 31;
        const int qr = l >> 2, qc = l & 3;
        const int nbase = w * 16;

        for (int i = 0, tile = blockIdx.x; tile < ntiles; tile += gridDim.x, i++) {
            const int b = i & 1;
            BAR_SYNC(1 + b, NT1);
            const uint32_t aHi = sb + L1_A0 + b * L1_ABUF;
            const uint32_t aLo = aHi + L1_AHALF;
            const int slot0 = tile * TILE1;

            float acc[2][2][4];
            #pragma unroll
            for (int t = 0; t < 2; t++)
                #pragma unroll
                for (int j = 0; j < 2; j++)
                    #pragma unroll
                    for (int u = 0; u < 4; u++) acc[t][j][u] = 0.f;

            #pragma unroll 2
            for (int ks = 0; ks < 16; ks++) {
                const int k0 = ks * 16;
                uint32_t ah[2][4], al[2][4];
                #pragma unroll
                for (int t = 0; t < 2; t++) {
                    const uint32_t r0 = (uint32_t)(t * 16 + qr) * (KSTR * 2);
                    const uint32_t r1 = r0 + 8 * (KSTR * 2);
                    const uint32_t cA = (uint32_t)(k0 + 2 * qc) * 2;
                    ah[t][0] = lds32(aHi + r0 + cA);  ah[t][1] = lds32(aHi + r1 + cA);
                    ah[t][2] = lds32(aHi + r0 + cA + 16); ah[t][3] = lds32(aHi + r1 + cA + 16);
                    al[t][0] = lds32(aLo + r0 + cA);  al[t][1] = lds32(aLo + r1 + cA);
                    al[t][2] = lds32(aLo + r0 + cA + 16); al[t][3] = lds32(aLo + r1 + cA + 16);
                }
                uint32_t bh[2][2], bl[2][2];
                #pragma unroll
                for (int j = 0; j < 2; j++) {
                    const uint32_t nrow = (uint32_t)(nbase + j * 8 + qr) * (KSTR * 2);
                    const uint32_t cB = (uint32_t)(k0 + 2 * qc) * 2;
                    bh[j][0] = lds32(sb + L1_BHI + nrow + cB);
                    bh[j][1] = lds32(sb + L1_BHI + nrow + cB + 16);
                    bl[j][0] = lds32(sb + L1_BLO + nrow + cB);
                    bl[j][1] = lds32(sb + L1_BLO + nrow + cB + 16);
                }
                #pragma unroll
                for (int t = 0; t < 2; t++)
                    #pragma unroll
                    for (int j = 0; j < 2; j++) {
                        mma_bf16(acc[t][j], ah[t][0], ah[t][1], ah[t][2], ah[t][3],
                                 bh[j][0], bh[j][1]);
                        mma_bf16(acc[t][j], ah[t][0], ah[t][1], ah[t][2], ah[t][3],
                                 bl[j][0], bl[j][1]);
                        mma_bf16(acc[t][j], al[t][0], al[t][1], al[t][2], al[t][3],
                                 bh[j][0], bh[j][1]);
                    }
            }
            BAR_ARRIVE(3 + b, NT1);

            #pragma unroll
            for (int t = 0; t < 2; t++) {
                const int nodeA = g_list[min(slot0 + t * 16 + qr, cnt - 1)];
                const int nodeB = g_list[min(slot0 + t * 16 + qr + 8, cnt - 1)];
                #pragma unroll
                for (int j = 0; j < 2; j++) {
                    const int n = nbase + j * 8 + 2 * qc;
                    const float bi0 = biass[n], bi1 = biass[n + 1];
                    float2 v0, v1;
                    v0.x = fmaxf(acc[t][j][0] + bi0, 0.f);
                    v0.y = fmaxf(acc[t][j][1] + bi1, 0.f);
                    v1.x = fmaxf(acc[t][j][2] + bi0, 0.f);
                    v1.y = fmaxf(acc[t][j][3] + bi1, 0.f);
                    *(float2*)(g_h1 + (size_t)nodeA * D + n) = v0;
                    *(float2*)(g_h1 + (size_t)nodeB * D + n) = v1;
                }
            }
        }
    }
}

// ---------------------------------------------------------------------------
// Layer 2: 32-node tile per block, grid=256, 2 blocks/SM.
// ---------------------------------------------------------------------------
extern "C" __global__ void __launch_bounds__(NT2, 2)
sage_layer2(const int* __restrict__ nidx, const int* __restrict__ batch,
            float* __restrict__ out)
{
    extern __shared__ char smem[];
    const uint32_t sb = smem_u32(smem);
    float* biass = (float*)(smem + L2_BIAS);

    const int tid = threadIdx.x;
    if (tid < 64) biass[tid] = g_b2p[tid];

    // stage W2p split+transposed: B[n][k] = W2p[k][n]
    for (int i = tid; i < 256 * 64; i += NT2) {
        const int k = i >> 6, n = i & 63;
        const float w = g_W2p[i];
        const float h = bfr(w);
        *(__nv_bfloat16*)(smem + L2_BHI + (n * KSTR + k) * 2) = __float2bfloat16_rn(w);
        *(__nv_bfloat16*)(smem + L2_BLO + (n * KSTR + k) * 2) = __float2bfloat16_rn(w - h);
    }

    char* Ahi = smem + L2_AHI;
    char* Alo = smem + L2_ALO;
    const int pos0 = blockIdx.x * TILE2;
    #pragma unroll
    for (int it = 0; it < 2; it++) {
        const int lin = tid + it * NT2;      // 0..1023
        const int nn  = lin >> 5;            // node 0..31 (warp-uniform)
        const int d4  = lin & 31;
        const int bnode = __ldg(batch + pos0 + nn);
        const int4* np = (const int4*)(nidx + (size_t)bnode * S);
        const int4 na = np[0], nb4 = np[1], nc = np[2], nd = np[3];
        const int nb[16] = {na.x, na.y, na.z, na.w, nb4.x, nb4.y, nb4.z, nb4.w,
                            nc.x, nc.y, nc.z, nc.w, nd.x, nd.y, nd.z, nd.w};
        gather_split(g_h1, nb, bnode, nn, d4, Ahi, Alo);
    }
    __syncthreads();

    // ---- MMA: 16 warps; warp w -> m-tile (w>>3), n-tile (w&7)*8 ----
    const int w  = tid >> 5;
    const int l  = tid & 31;
    const int qr = l >> 2, qc = l & 3;
    const int mt = w >> 3;            // 0..1
    const int nbase = (w & 7) * 8;

    const uint32_t aHi = sb + L2_AHI;
    const uint32_t aLo = sb + L2_ALO;

    float acc[4];
    #pragma unroll
    for (int u = 0; u < 4; u++) acc[u] = 0.f;

    #pragma unroll 4
    for (int ks = 0; ks < 16; ks++) {
        const int k0 = ks * 16;
        uint32_t ah[4], al[4];
        {
            const uint32_t r0 = (uint32_t)(mt * 16 + qr) * (KSTR * 2);
            const uint32_t r1 = r0 + 8 * (KSTR * 2);
            const uint32_t cA = (uint32_t)(k0 + 2 * qc) * 2;
            ah[0] = lds32(aHi + r0 + cA);      ah[1] = lds32(aHi + r1 + cA);
            ah[2] = lds32(aHi + r0 + cA + 16); ah[3] = lds32(aHi + r1 + cA + 16);
            al[0] = lds32(aLo + r0 + cA);      al[1] = lds32(aLo + r1 + cA);
            al[2] = lds32(aLo + r0 + cA + 16); al[3] = lds32(aLo + r1 + cA + 16);
        }
        uint32_t bh[2], bl[2];
        {
            const uint32_t nrow = (uint32_t)(nbase + qr) * (KSTR * 2);
            const uint32_t cB = (uint32_t)(k0 + 2 * qc) * 2;
            bh[0] = lds32(sb + L2_BHI + nrow + cB);
            bh[1] = lds32(sb + L2_BHI + nrow + cB + 16);
            bl[0] = lds32(sb + L2_BLO + nrow + cB);
            bl[1] = lds32(sb + L2_BLO + nrow + cB + 16);
        }
        mma_bf16(acc, ah[0], ah[1], ah[2], ah[3], bh[0], bh[1]);
        mma_bf16(acc, ah[0], ah[1], ah[2], ah[3], bl[0], bl[1]);
        mma_bf16(acc, al[0], al[1], al[2], al[3], bh[0], bh[1]);
    }

    const int r0 = pos0 + mt * 16 + qr;
    const int n = nbase + 2 * qc;
    const float bi0 = biass[n], bi1 = biass[n + 1];
    float2 v0, v1;
    v0.x = acc[0] + bi0; v0.y = acc[1] + bi1;
    v1.x = acc[2] + bi0; v1.y = acc[3] + bi1;
    *(float2*)(out + (size_t)r0 * 64 + n) = v0;
    *(float2*)(out + (size_t)(r0 + 8) * 64 + n) = v1;
}

// ---------------------------------------------------------------------------
extern "C" void kernel_launch(void* const* d_in, const int* in_sizes, int n_in,
                              void* d_out, int out_size)
{
    const float* x    = (const float*)d_in[0];
    const int*   nidx = (const int*)  d_in[1];
    const int*   batch= (const int*)  d_in[2];
    const float* W1   = (const float*)d_in[3];
    const float* b1   = (const float*)d_in[4];
    const float* W2   = (const float*)d_in[5];
    const float* b2   = (const float*)d_in[6];
    const float* Wout = (const float*)d_in[7];
    const float* bout = (const float*)d_in[8];
    float* out = (float*)d_out;

    cudaFuncSetAttribute((const void*)sage_layer1,
                         cudaFuncAttributeMaxDynamicSharedMemorySize, SMEM1_SZ);
    cudaFuncSetAttribute((const void*)sage_layer2,
                         cudaFuncAttributeMaxDynamicSharedMemorySize, SMEM2_SZ);

    void* p_mark; void* p_cnt;
    cudaGetSymbolAddress(&p_mark, g_mark);
    cudaGetSymbolAddress(&p_cnt,  g_cnt);
    cudaMemsetAsync(p_mark, 0, NNODES);
    cudaMemsetAsync(p_cnt,  0, sizeof(int));

    mark_prep<<<128, 256>>>(batch, nidx, W2, b2, Wout, bout);
    compact_frontier<<<(NNODES + 255) / 256, 256>>>();
    sage_layer1<<<152, NT1, SMEM1_SZ>>>(x, nidx, W1, b1);
    sage_layer2<<<256, NT2, SMEM2_SZ>>>(nidx, batch, out);
}